// round 5
// baseline (speedup 1.0000x reference)
#include <cuda_runtime.h>
#include <cstdint>
#include <cstddef>

#define B_    8
#define T_    8192
#define D_    512
#define H_    4
#define P_    24
#define HD_   128
#define TOPK_ 12
#define NC_   16
#define CHUNK_ 512

// ---------------- scratch (static device globals; no allocation) ----------------
__device__ __align__(16) float g_xn[(size_t)B_ * T_ * D_];   // tf32-rounded LN output
__device__ __align__(16) float g_K [(size_t)B_ * T_ * D_];
__device__ __align__(16) float g_V [(size_t)B_ * T_ * D_];
__device__ __align__(16) float g_Wt[2 * D_ * D_];            // tf32-rounded Wk, Wv
__device__ float g_Qh[H_ * P_ * HD_];
__device__ float g_part[(size_t)B_ * H_ * NC_ * P_ * 130];
__device__ float g_pt[B_ * P_ * D_];
__device__ float g_z [B_ * D_];
__device__ float g_hid[B_ * D_];

// ---------------- helpers ----------------
__device__ __forceinline__ float tf32r(float v) {
    uint32_t o;
    asm("cvt.rna.tf32.f32 %0, %1;" : "=r"(o) : "f"(v));
    return __uint_as_float(o);
}
__device__ __forceinline__ uint32_t smem_u32(const void* p) {
    uint32_t a;
    asm("{ .reg .u64 t; cvta.to.shared.u64 t, %1; cvt.u32.u64 %0, t; }" : "=r"(a) : "l"(p));
    return a;
}
__device__ __forceinline__ void cp16(uint32_t s, const void* g) {
    asm volatile("cp.async.cg.shared.global [%0], [%1], 16;" :: "r"(s), "l"(g) : "memory");
}
__device__ __forceinline__ void cp_commit() {
    asm volatile("cp.async.commit_group;" ::: "memory");
}
template <int N> __device__ __forceinline__ void cp_wait() {
    asm volatile("cp.async.wait_group %0;" :: "n"(N) : "memory");
}
__device__ __forceinline__ void mma_tf32(float* c,
                                         uint32_t a0, uint32_t a1, uint32_t a2, uint32_t a3,
                                         uint32_t b0, uint32_t b1) {
    asm volatile("mma.sync.aligned.m16n8k8.row.col.f32.tf32.tf32.f32 "
                 "{%0,%1,%2,%3}, {%4,%5,%6,%7}, {%8,%9}, {%0,%1,%2,%3};"
                 : "+f"(c[0]), "+f"(c[1]), "+f"(c[2]), "+f"(c[3])
                 : "r"(a0), "r"(a1), "r"(a2), "r"(a3), "r"(b0), "r"(b1));
}

// ---------------- 1. LayerNorm (writes tf32-rounded xn) ----------------
__global__ __launch_bounds__(256) void ln_kernel(const float* __restrict__ x,
                                                 const float* __restrict__ gw,
                                                 const float* __restrict__ bw) {
    int lane = threadIdx.x & 31;
    size_t row = (size_t)blockIdx.x * 8 + (threadIdx.x >> 5);
    const float* xr = x + row * D_;
    float4 v[4];
    float s = 0.f, sq = 0.f;
#pragma unroll
    for (int j = 0; j < 4; j++) {
        v[j] = *(const float4*)&xr[lane * 4 + j * 128];
        s  += v[j].x + v[j].y + v[j].z + v[j].w;
        sq += v[j].x * v[j].x + v[j].y * v[j].y + v[j].z * v[j].z + v[j].w * v[j].w;
    }
#pragma unroll
    for (int o = 16; o > 0; o >>= 1) {
        s  += __shfl_xor_sync(0xffffffffu, s,  o);
        sq += __shfl_xor_sync(0xffffffffu, sq, o);
    }
    float mu   = s * (1.f / 512.f);
    float var  = sq * (1.f / 512.f) - mu * mu;
    float rstd = rsqrtf(var + 1e-5f);
    float* orow = g_xn + row * D_;
#pragma unroll
    for (int j = 0; j < 4; j++) {
        int c = lane * 4 + j * 128;
        float4 gv = *(const float4*)&gw[c];
        float4 bv = *(const float4*)&bw[c];
        float4 o;
        o.x = tf32r((v[j].x - mu) * rstd * gv.x + bv.x);
        o.y = tf32r((v[j].y - mu) * rstd * gv.y + bv.y);
        o.z = tf32r((v[j].z - mu) * rstd * gv.z + bv.z);
        o.w = tf32r((v[j].w - mu) * rstd * gv.w + bv.w);
        *(float4*)&orow[c] = o;
    }
}

// ---------------- 1b. round W matrices to tf32 ----------------
__global__ __launch_bounds__(256) void round_w(const float* __restrict__ Wk,
                                               const float* __restrict__ Wv) {
    int i = blockIdx.x * 256 + threadIdx.x;
    g_Wt[i]             = tf32r(Wk[i]);
    g_Wt[D_ * D_ + i]   = tf32r(Wv[i]);
}

// ---------------- 2. tf32 mma.sync GEMM: C = xn @ W^T ----------------
#define BK 32
#define ASTRIDE 36
#define BUF_FLOATS (128 * ASTRIDE)   // 4608

__global__ __launch_bounds__(256, 2) void gemm_mma() {
    extern __shared__ __align__(16) float sm[];
    float* As = sm;
    float* Ws = sm + 2 * BUF_FLOATS;
    const uint32_t smA = smem_u32(As);
    const uint32_t smW = smem_u32(Ws);

    const int tid = threadIdx.x;
    const int wid = tid >> 5, lane = tid & 31;
    const int which = blockIdx.x >> 2;
    const int n0 = (blockIdx.x & 3) * 128;
    const size_t m0 = (size_t)blockIdx.y * 128;
    const float* Wt = g_Wt + (size_t)which * (D_ * D_);
    float* C = which ? g_V : g_K;

    const int lrow = tid >> 1;
    const int lcb  = (tid & 1) * 16;
    const float* ga0 = g_xn + (m0 + lrow) * D_ + lcb;
    const float* gw0 = Wt + (size_t)(n0 + lrow) * D_ + lcb;
    const uint32_t sa0 = smA + (uint32_t)(lrow * ASTRIDE + lcb) * 4;
    const uint32_t sw0 = smW + (uint32_t)(lrow * ASTRIDE + lcb) * 4;

    const int wm = (wid >> 2) * 64;
    const int wn = (wid & 3) * 32;
    const int g  = lane >> 2;
    const int t  = lane & 3;

    float c[4][4][4];
#pragma unroll
    for (int mi = 0; mi < 4; mi++)
#pragma unroll
        for (int ni = 0; ni < 4; ni++)
#pragma unroll
            for (int j = 0; j < 4; j++) c[mi][ni][j] = 0.f;

#pragma unroll
    for (int j = 0; j < 4; j++) {
        cp16(sa0 + j * 16, ga0 + j * 4);
        cp16(sw0 + j * 16, gw0 + j * 4);
    }
    cp_commit();

    int buf = 0;
#pragma unroll 1
    for (int kt = 0; kt < 16; ++kt) {
        if (kt < 15) {
            int k0 = (kt + 1) * BK;
            int nb = buf ^ 1;
#pragma unroll
            for (int j = 0; j < 4; j++) {
                cp16(sa0 + (uint32_t)nb * BUF_FLOATS * 4 + j * 16, ga0 + k0 + j * 4);
                cp16(sw0 + (uint32_t)nb * BUF_FLOATS * 4 + j * 16, gw0 + k0 + j * 4);
            }
            cp_commit();
            cp_wait<1>();
        } else {
            cp_wait<0>();
        }
        __syncthreads();

        const float* Ab = As + buf * BUF_FLOATS;
        const float* Wb = Ws + buf * BUF_FLOATS;
#pragma unroll
        for (int ks = 0; ks < 4; ks++) {
            uint32_t a[4][4], bfr[4][2];
#pragma unroll
            for (int mi = 0; mi < 4; mi++) {
                const float* ap = Ab + (wm + mi * 16 + g) * ASTRIDE + ks * 8 + t;
                a[mi][0] = __float_as_uint(ap[0]);
                a[mi][1] = __float_as_uint(ap[8 * ASTRIDE]);
                a[mi][2] = __float_as_uint(ap[4]);
                a[mi][3] = __float_as_uint(ap[8 * ASTRIDE + 4]);
            }
#pragma unroll
            for (int ni = 0; ni < 4; ni++) {
                const float* bp = Wb + (wn + ni * 8 + g) * ASTRIDE + ks * 8 + t;
                bfr[ni][0] = __float_as_uint(bp[0]);
                bfr[ni][1] = __float_as_uint(bp[4]);
            }
#pragma unroll
            for (int mi = 0; mi < 4; mi++)
#pragma unroll
                for (int ni = 0; ni < 4; ni++)
                    mma_tf32(c[mi][ni],
                             a[mi][0], a[mi][1], a[mi][2], a[mi][3],
                             bfr[ni][0], bfr[ni][1]);
        }
        __syncthreads();
        buf ^= 1;
    }

#pragma unroll
    for (int mi = 0; mi < 4; mi++) {
#pragma unroll
        for (int ni = 0; ni < 4; ni++) {
            size_t r0 = m0 + wm + mi * 16 + g;
            int col = n0 + wn + ni * 8 + t * 2;
            *(float2*)&C[r0 * D_ + col]        = make_float2(c[mi][ni][0], c[mi][ni][1]);
            *(float2*)&C[(r0 + 8) * D_ + col]  = make_float2(c[mi][ni][2], c[mi][ni][3]);
        }
    }
}

// ---------------- 3. Qh: grid (P, H), 512 threads ----------------
__global__ __launch_bounds__(512) void qh_kernel(const float* __restrict__ proto,
                                                 const float* __restrict__ Wq) {
    __shared__ float pr[D_];
    __shared__ float qp[HD_];
    __shared__ float sinv;
    int p = blockIdx.x, h = blockIdx.y, tid = threadIdx.x;
    pr[tid] = proto[p * D_ + tid];
    __syncthreads();
    int nl = tid >> 2, part = tid & 3;
    const float* wr = Wq + (size_t)(h * HD_ + nl) * D_ + part * 128;
    const float* pp = pr + part * 128;
    float a = 0.f;
#pragma unroll 8
    for (int k = 0; k < 128; k += 4) {
        float4 w4 = *(const float4*)&wr[k];
        a += w4.x * pp[k] + w4.y * pp[k + 1] + w4.z * pp[k + 2] + w4.w * pp[k + 3];
    }
    a += __shfl_xor_sync(0xffffffffu, a, 1);
    a += __shfl_xor_sync(0xffffffffu, a, 2);
    if (part == 0) qp[nl] = a;
    __syncthreads();
    if (tid < 32) {
        float sq = 0.f;
#pragma unroll
        for (int j = 0; j < 4; j++) { float tv = qp[tid + 32 * j]; sq += tv * tv; }
#pragma unroll
        for (int o = 16; o > 0; o >>= 1) sq += __shfl_xor_sync(0xffffffffu, sq, o);
        if (tid == 0) sinv = 1.f / fmaxf(sqrtf(sq), 1e-12f);
    }
    __syncthreads();
    if (tid < HD_) g_Qh[(h * P_ + p) * HD_ + tid] = qp[tid] * sinv;
}

// ---------------- 4. attention via tf32 mma with split precision ----------------
// grid (NC_, H_, B_), 256 threads, smem 169920 B.
// Strides chosen for conflict-free m16n8k8 fragment loads.
#define QSTR 132
#define KSTR 132
#define VSTR 136
#define SSTR 516
#define oQhi 0
#define oQlo 4224
#define oThi 8448
#define oTlo 17152
#define oSs  25856
#define oNm  42368
#define oM   42432
#define oL   42456
#define ATT_SMEM (42480 * 4)

__global__ __launch_bounds__(256) void att_mma() {
    extern __shared__ __align__(16) float sm[];
    float* Qhi = sm + oQhi;
    float* Qlo = sm + oQlo;
    float* Thi = sm + oThi;
    float* Tlo = sm + oTlo;
    float* Ss  = sm + oSs;
    float* Nm  = sm + oNm;
    float* Msm = sm + oM;
    float* Lsm = sm + oL;

    const int tid = threadIdx.x;
    const int w = tid >> 5, lane = tid & 31;
    const int g = lane >> 2, t = lane & 3;
    const int cz = blockIdx.x, h = blockIdx.y, b = blockIdx.z;

    // ---- Q prep: rows 0..23 real, 24..31 zero; hi/lo split ----
    for (int i = tid; i < 32 * HD_; i += 256) {
        int p = i >> 7, d = i & 127;
        float v = (p < P_) ? g_Qh[(h * P_ + p) * HD_ + d] : 0.f;
        float hi = tf32r(v);
        Qhi[p * QSTR + d] = hi;
        Qlo[p * QSTR + d] = tf32r(v - hi);
    }

    const int lrow = tid >> 2, lcg = (tid & 3) * 32;

    // ================= scores =================
#pragma unroll 1
    for (int st = 0; st < 8; ++st) {
        __syncthreads();
        // load K tile (64 tokens x 128 dims), split hi/lo, row norms
        {
            const float4* src = (const float4*)(g_K +
                ((size_t)(b * T_ + cz * CHUNK_ + st * 64 + lrow)) * D_ + h * HD_ + lcg);
            float nn = 0.f;
#pragma unroll
            for (int j = 0; j < 8; j++) {
                float4 v = src[j];
                float4 hi, lo;
                hi.x = tf32r(v.x); lo.x = tf32r(v.x - hi.x);
                hi.y = tf32r(v.y); lo.y = tf32r(v.y - hi.y);
                hi.z = tf32r(v.z); lo.z = tf32r(v.z - hi.z);
                hi.w = tf32r(v.w); lo.w = tf32r(v.w - hi.w);
                *(float4*)&Thi[lrow * KSTR + lcg + j * 4] = hi;
                *(float4*)&Tlo[lrow * KSTR + lcg + j * 4] = lo;
                nn += v.x * v.x + v.y * v.y + v.z * v.z + v.w * v.w;
            }
            nn += __shfl_xor_sync(0xffffffffu, nn, 1);
            nn += __shfl_xor_sync(0xffffffffu, nn, 2);
            if ((tid & 3) == 0) Nm[lrow] = nn;
        }
        __syncthreads();

        float c[2][4] = {};
#pragma unroll
        for (int kt = 0; kt < 16; kt++) {
            uint32_t ah[2][4], al[2][4];
#pragma unroll
            for (int mi = 0; mi < 2; mi++) {
                const float* q0 = &Qhi[(mi * 16 + g) * QSTR + kt * 8 + t];
                ah[mi][0] = __float_as_uint(q0[0]);
                ah[mi][1] = __float_as_uint(q0[8 * QSTR]);
                ah[mi][2] = __float_as_uint(q0[4]);
                ah[mi][3] = __float_as_uint(q0[8 * QSTR + 4]);
                const float* q1 = &Qlo[(mi * 16 + g) * QSTR + kt * 8 + t];
                al[mi][0] = __float_as_uint(q1[0]);
                al[mi][1] = __float_as_uint(q1[8 * QSTR]);
                al[mi][2] = __float_as_uint(q1[4]);
                al[mi][3] = __float_as_uint(q1[8 * QSTR + 4]);
            }
            const float* kb = &Thi[(w * 8 + g) * KSTR + kt * 8 + t];
            uint32_t bh0 = __float_as_uint(kb[0]), bh1 = __float_as_uint(kb[4]);
            const float* kl = &Tlo[(w * 8 + g) * KSTR + kt * 8 + t];
            uint32_t bl0 = __float_as_uint(kl[0]), bl1 = __float_as_uint(kl[4]);
#pragma unroll
            for (int mi = 0; mi < 2; mi++) {
                mma_tf32(c[mi], ah[mi][0], ah[mi][1], ah[mi][2], ah[mi][3], bh0, bh1);
                mma_tf32(c[mi], ah[mi][0], ah[mi][1], ah[mi][2], ah[mi][3], bl0, bl1);
                mma_tf32(c[mi], al[mi][0], al[mi][1], al[mi][2], al[mi][3], bh0, bh1);
            }
        }
        int c0 = w * 8 + t * 2;
        float inv0 = 1.f / (fmaxf(sqrtf(Nm[c0]),     1e-12f) * 0.07f);
        float inv1 = 1.f / (fmaxf(sqrtf(Nm[c0 + 1]), 1e-12f) * 0.07f);
#pragma unroll
        for (int mi = 0; mi < 2; mi++) {
            int r0 = mi * 16 + g;
            Ss[r0 * SSTR + st * 64 + c0]           = c[mi][0] * inv0;
            Ss[r0 * SSTR + st * 64 + c0 + 1]       = c[mi][1] * inv1;
            Ss[(r0 + 8) * SSTR + st * 64 + c0]     = c[mi][2] * inv0;
            Ss[(r0 + 8) * SSTR + st * 64 + c0 + 1] = c[mi][3] * inv1;
        }
    }
    __syncthreads();

    // ================= softmax (rows 0..23) =================
#pragma unroll 1
    for (int rr = 0; rr < 3; ++rr) {
        int p = w + rr * 8;
        float vals[16];
        float m = -3.4e38f;
#pragma unroll
        for (int j = 0; j < 16; j++) {
            vals[j] = Ss[p * SSTR + lane + 32 * j];
            m = fmaxf(m, vals[j]);
        }
#pragma unroll
        for (int o = 16; o > 0; o >>= 1) m = fmaxf(m, __shfl_xor_sync(0xffffffffu, m, o));
        float s = 0.f;
#pragma unroll
        for (int j = 0; j < 16; j++) {
            float e = expf(vals[j] - m);
            Ss[p * SSTR + lane + 32 * j] = e;
            s += e;
        }
#pragma unroll
        for (int o = 16; o > 0; o >>= 1) s += __shfl_xor_sync(0xffffffffu, s, o);
        if (lane == 0) { Msm[p] = m; Lsm[p] = s; }
    }

    // ================= PV =================
    float cp[2][2][4] = {};
#pragma unroll 1
    for (int st = 0; st < 8; ++st) {
        __syncthreads();
        {
            const float4* src = (const float4*)(g_V +
                ((size_t)(b * T_ + cz * CHUNK_ + st * 64 + lrow)) * D_ + h * HD_ + lcg);
#pragma unroll
            for (int j = 0; j < 8; j++) {
                float4 v = src[j];
                float4 hi, lo;
                hi.x = tf32r(v.x); lo.x = tf32r(v.x - hi.x);
                hi.y = tf32r(v.y); lo.y = tf32r(v.y - hi.y);
                hi.z = tf32r(v.z); lo.z = tf32r(v.z - hi.z);
                hi.w = tf32r(v.w); lo.w = tf32r(v.w - hi.w);
                *(float4*)&Thi[lrow * VSTR + lcg + j * 4] = hi;
                *(float4*)&Tlo[lrow * VSTR + lcg + j * 4] = lo;
            }
        }
        __syncthreads();

#pragma unroll
        for (int kt = 0; kt < 8; kt++) {
            uint32_t ah[2][4], al[2][4];
#pragma unroll
            for (int mi = 0; mi < 2; mi++) {
                const float* s0 = &Ss[(mi * 16 + g) * SSTR + st * 64 + kt * 8 + t];
                float a0 = s0[0], a1 = s0[8 * SSTR], a2 = s0[4], a3 = s0[8 * SSTR + 4];
                float h0 = tf32r(a0), h1 = tf32r(a1), h2 = tf32r(a2), h3 = tf32r(a3);
                ah[mi][0] = __float_as_uint(h0);
                ah[mi][1] = __float_as_uint(h1);
                ah[mi][2] = __float_as_uint(h2);
                ah[mi][3] = __float_as_uint(h3);
                al[mi][0] = __float_as_uint(tf32r(a0 - h0));
                al[mi][1] = __float_as_uint(tf32r(a1 - h1));
                al[mi][2] = __float_as_uint(tf32r(a2 - h2));
                al[mi][3] = __float_as_uint(tf32r(a3 - h3));
            }
#pragma unroll
            for (int nt = 0; nt < 2; nt++) {
                const float* vb = &Thi[(kt * 8 + t) * VSTR + w * 16 + nt * 8 + g];
                uint32_t bh0 = __float_as_uint(vb[0]);
                uint32_t bh1 = __float_as_uint(vb[4 * VSTR]);
                const float* vl = &Tlo[(kt * 8 + t) * VSTR + w * 16 + nt * 8 + g];
                uint32_t bl0 = __float_as_uint(vl[0]);
                uint32_t bl1 = __float_as_uint(vl[4 * VSTR]);
#pragma unroll
                for (int mi = 0; mi < 2; mi++) {
                    mma_tf32(cp[mi][nt], ah[mi][0], ah[mi][1], ah[mi][2], ah[mi][3], bh0, bh1);
                    mma_tf32(cp[mi][nt], ah[mi][0], ah[mi][1], ah[mi][2], ah[mi][3], bl0, bl1);
                    mma_tf32(cp[mi][nt], al[mi][0], al[mi][1], al[mi][2], al[mi][3], bh0, bh1);
                }
            }
        }
    }

    // ---- write partials ----
    size_t base = (((size_t)(b * H_ + h) * NC_ + cz) * P_) * 130;
#pragma unroll
    for (int mi = 0; mi < 2; mi++)
#pragma unroll
        for (int nt = 0; nt < 2; nt++)
#pragma unroll
            for (int j = 0; j < 4; j++) {
                int r = mi * 16 + g + ((j >> 1) ? 8 : 0);
                if (r < P_) {
                    int col = w * 16 + nt * 8 + t * 2 + (j & 1);
                    g_part[base + (size_t)r * 130 + 2 + col] = cp[mi][nt][j];
                }
            }
    if (tid < P_) {
        g_part[base + (size_t)tid * 130]     = Msm[tid];
        g_part[base + (size_t)tid * 130 + 1] = Lsm[tid];
    }
}

// ---------------- 5. merge ----------------
__global__ __launch_bounds__(128) void merge_kernel() {
    int p = blockIdx.x, h = blockIdx.y, b = blockIdx.z;
    int d = threadIdx.x;
    float M = -3.4e38f;
    for (int c = 0; c < NC_; c++) {
        const float* pp = g_part + (((size_t)(b * H_ + h) * NC_ + c) * P_ + p) * 130;
        M = fmaxf(M, pp[0]);
    }
    float L = 0.f, val = 0.f;
    for (int c = 0; c < NC_; c++) {
        const float* pp = g_part + (((size_t)(b * H_ + h) * NC_ + c) * P_ + p) * 130;
        float wgt = expf(pp[0] - M);
        L   += pp[1] * wgt;
        val += pp[2 + d] * wgt;
    }
    float out = (L > 0.f) ? val / L : 0.f;
    g_pt[(b * P_ + p) * D_ + h * HD_ + d] = out;
}

// ---------------- 6. topk ----------------
__global__ __launch_bounds__(256) void topk_kernel() {
    int b = blockIdx.x, tid = threadIdx.x, w = tid >> 5, lane = tid & 31;
    __shared__ float ss[P_];
    __shared__ int idxs[TOPK_];
#pragma unroll 1
    for (int rr = 0; rr < 3; rr++) {
        int p = w + rr * 8;
        const float* pr = g_pt + (b * P_ + p) * D_;
        float sq = 0.f;
#pragma unroll
        for (int j = 0; j < 16; j++) { float tv = pr[lane + 32 * j]; sq += tv * tv; }
#pragma unroll
        for (int o = 16; o > 0; o >>= 1) sq += __shfl_xor_sync(0xffffffffu, sq, o);
        if (lane == 0) ss[p] = sq;
    }
    __syncthreads();
    if (tid == 0) {
        unsigned used = 0;
        for (int i = 0; i < TOPK_; i++) {
            int best = -1; float bv = -3.4e38f;
            for (int p = 0; p < P_; p++)
                if (!((used >> p) & 1) && ss[p] > bv) { bv = ss[p]; best = p; }
            used |= 1u << best;
            idxs[i] = best;
        }
    }
    __syncthreads();
    for (int d = tid; d < D_; d += 256) {
        float s = 0.f;
        for (int i = 0; i < TOPK_; i++) s += g_pt[(b * P_ + idxs[i]) * D_ + d];
        g_z[b * D_ + d] = s * (1.f / TOPK_);
    }
}

// ---------------- 7. MLP ----------------
__global__ __launch_bounds__(128) void mlp_kernel(int in_sel, const float* __restrict__ W,
                                                  const float* __restrict__ bias,
                                                  float* __restrict__ out_ext, int act) {
    __shared__ float zs[D_];
    int b = blockIdx.y, tid = threadIdx.x;
    int n = blockIdx.x * 128 + tid;
    const float* in = in_sel ? g_hid : g_z;
    for (int i = tid; i < D_; i += 128) zs[i] = in[b * D_ + i];
    __syncthreads();
    const float* wr = W + (size_t)n * D_;
    float s = bias[n];
    for (int k = 0; k < D_; k += 4) {
        float4 w4 = *(const float4*)&wr[k];
        s += w4.x * zs[k] + w4.y * zs[k + 1] + w4.z * zs[k + 2] + w4.w * zs[k + 3];
    }
    if (act) s = s / (1.f + expf(-s));
    float* out = out_ext ? out_ext : g_hid;
    out[b * D_ + n] = s;
}

// ---------------- launch ----------------
extern "C" void kernel_launch(void* const* d_in, const int* in_sizes, int n_in,
                              void* d_out, int out_size) {
    (void)in_sizes; (void)n_in; (void)out_size;
    const float* x     = (const float*)d_in[0];
    const float* proto = (const float*)d_in[1];
    const float* ln_g  = (const float*)d_in[2];
    const float* ln_b  = (const float*)d_in[3];
    const float* Wq    = (const float*)d_in[4];
    const float* Wk    = (const float*)d_in[5];
    const float* Wv    = (const float*)d_in[6];
    const float* W1    = (const float*)d_in[7];
    const float* b1    = (const float*)d_in[8];
    const float* W2    = (const float*)d_in[9];
    const float* b2    = (const float*)d_in[10];
    float* out = (float*)d_out;

    const int gemm_smem = 4 * BUF_FLOATS * 4;   // 73728 bytes
    cudaFuncSetAttribute(gemm_mma, cudaFuncAttributeMaxDynamicSharedMemorySize, gemm_smem);
    cudaFuncSetAttribute(att_mma, cudaFuncAttributeMaxDynamicSharedMemorySize, ATT_SMEM);

    ln_kernel<<<(B_ * T_) / 8, 256>>>(x, ln_g, ln_b);
    round_w<<<(D_ * D_) / 256, 256>>>(Wk, Wv);
    gemm_mma<<<dim3(8, 512), 256, gemm_smem>>>();
    qh_kernel<<<dim3(P_, H_), 512>>>(proto, Wq);
    att_mma<<<dim3(NC_, H_, B_), 256, ATT_SMEM>>>();
    merge_kernel<<<dim3(P_, H_, B_), 128>>>();
    topk_kernel<<<B_, 256>>>();
    mlp_kernel<<<dim3(4, B_), 128>>>(0, W1, b1, nullptr, 1);
    mlp_kernel<<<dim3(4, B_), 128>>>(1, W2, b2, out, 0);
}

// round 6
// speedup vs baseline: 1.0945x; 1.0945x over previous
#include <cuda_runtime.h>
#include <cuda_bf16.h>
#include <cstdint>
#include <cstddef>

#define B_    8
#define T_    8192
#define D_    512
#define H_    4
#define P_    24
#define HD_   128
#define TOPK_ 12
#define NC_   16
#define CHUNK_ 512

// ---------------- scratch (static device globals; no allocation) ----------------
__device__ __align__(16) __nv_bfloat16 g_xh[(size_t)B_ * T_ * D_];  // xn hi (bf16)
__device__ __align__(16) __nv_bfloat16 g_xl[(size_t)B_ * T_ * D_];  // xn lo (bf16)
__device__ __align__(16) __nv_bfloat16 g_Wh[2 * D_ * D_];           // Wk,Wv hi
__device__ __align__(16) __nv_bfloat16 g_Wl[2 * D_ * D_];           // Wk,Wv lo
__device__ __align__(16) float g_K [(size_t)B_ * T_ * D_];
__device__ __align__(16) float g_V [(size_t)B_ * T_ * D_];
__device__ float g_Qh[H_ * P_ * HD_];
__device__ float g_part[(size_t)B_ * H_ * NC_ * P_ * 130];
__device__ float g_pt[B_ * P_ * D_];
__device__ float g_z [B_ * D_];
__device__ float g_hid[B_ * D_];

// ---------------- helpers ----------------
__device__ __forceinline__ uint32_t smem_u32(const void* p) {
    uint32_t a;
    asm("{ .reg .u64 t; cvta.to.shared.u64 t, %1; cvt.u32.u64 %0, t; }" : "=r"(a) : "l"(p));
    return a;
}
__device__ __forceinline__ void cp16(uint32_t s, const void* g) {
    asm volatile("cp.async.cg.shared.global [%0], [%1], 16;" :: "r"(s), "l"(g) : "memory");
}
__device__ __forceinline__ void cp_commit() {
    asm volatile("cp.async.commit_group;" ::: "memory");
}
template <int N> __device__ __forceinline__ void cp_wait() {
    asm volatile("cp.async.wait_group %0;" :: "n"(N) : "memory");
}
__device__ __forceinline__ void mma_bf16(float* c,
                                         uint32_t a0, uint32_t a1, uint32_t a2, uint32_t a3,
                                         uint32_t b0, uint32_t b1) {
    asm volatile("mma.sync.aligned.m16n8k16.row.col.f32.bf16.bf16.f32 "
                 "{%0,%1,%2,%3}, {%4,%5,%6,%7}, {%8,%9}, {%0,%1,%2,%3};"
                 : "+f"(c[0]), "+f"(c[1]), "+f"(c[2]), "+f"(c[3])
                 : "r"(a0), "r"(a1), "r"(a2), "r"(a3), "r"(b0), "r"(b1));
}
// split v into bf16 hi/lo
__device__ __forceinline__ void bsplit(float v, __nv_bfloat16& h, __nv_bfloat16& l) {
    h = __float2bfloat16_rn(v);
    l = __float2bfloat16_rn(v - __bfloat162float(h));
}

// ---------------- 1. LayerNorm -> bf16 hi/lo split ----------------
__global__ __launch_bounds__(256) void ln_kernel(const float* __restrict__ x,
                                                 const float* __restrict__ gw,
                                                 const float* __restrict__ bw) {
    int lane = threadIdx.x & 31;
    size_t row = (size_t)blockIdx.x * 8 + (threadIdx.x >> 5);
    const float* xr = x + row * D_;
    float4 v[4];
    float s = 0.f, sq = 0.f;
#pragma unroll
    for (int j = 0; j < 4; j++) {
        v[j] = *(const float4*)&xr[lane * 4 + j * 128];
        s  += v[j].x + v[j].y + v[j].z + v[j].w;
        sq += v[j].x * v[j].x + v[j].y * v[j].y + v[j].z * v[j].z + v[j].w * v[j].w;
    }
#pragma unroll
    for (int o = 16; o > 0; o >>= 1) {
        s  += __shfl_xor_sync(0xffffffffu, s,  o);
        sq += __shfl_xor_sync(0xffffffffu, sq, o);
    }
    float mu   = s * (1.f / 512.f);
    float var  = sq * (1.f / 512.f) - mu * mu;
    float rstd = rsqrtf(var + 1e-5f);
#pragma unroll
    for (int j = 0; j < 4; j++) {
        int c = lane * 4 + j * 128;
        float4 gv = *(const float4*)&gw[c];
        float4 bv = *(const float4*)&bw[c];
        float o0 = (v[j].x - mu) * rstd * gv.x + bv.x;
        float o1 = (v[j].y - mu) * rstd * gv.y + bv.y;
        float o2 = (v[j].z - mu) * rstd * gv.z + bv.z;
        float o3 = (v[j].w - mu) * rstd * gv.w + bv.w;
        __nv_bfloat16 h[4], l[4];
        bsplit(o0, h[0], l[0]); bsplit(o1, h[1], l[1]);
        bsplit(o2, h[2], l[2]); bsplit(o3, h[3], l[3]);
        *(uint2*)&g_xh[row * D_ + c] = *(uint2*)h;
        *(uint2*)&g_xl[row * D_ + c] = *(uint2*)l;
    }
}

// ---------------- 1b. split W matrices into bf16 hi/lo ----------------
__global__ __launch_bounds__(256) void round_w(const float* __restrict__ Wk,
                                               const float* __restrict__ Wv) {
    int i = blockIdx.x * 256 + threadIdx.x;
    __nv_bfloat16 h, l;
    bsplit(Wk[i], h, l);
    g_Wh[i] = h; g_Wl[i] = l;
    bsplit(Wv[i], h, l);
    g_Wh[D_ * D_ + i] = h; g_Wl[D_ * D_ + i] = l;
}

// ---------------- 2. bf16-split mma GEMM: C = xn @ W^T ----------------
// grid (8, 512): x = which*4 + ntile, y = m tile. CTA 128x128, K in 16 chunks of 32.
// smem rows: 32 bf16 (64B) padded to 80B (20 words) -> conflict-free frag loads.
#define GSTR 20                    // words per row
#define TILE_WORDS (128 * GSTR)    // 2560 words = 10240 B per part
#define BUF_WORDS  (4 * TILE_WORDS)
#define GEMM_SMEM  (2 * BUF_WORDS * 4)   // 81920 B

__global__ __launch_bounds__(256, 2) void gemm_bf16() {
    extern __shared__ __align__(16) uint32_t smw[];
    const uint32_t sb = smem_u32(smw);

    const int tid = threadIdx.x;
    const int wid = tid >> 5, lane = tid & 31;
    const int which = blockIdx.x >> 2;
    const int n0 = (blockIdx.x & 3) * 128;
    const size_t m0 = (size_t)blockIdx.y * 128;

    const __nv_bfloat16* Ah_g = g_xh;
    const __nv_bfloat16* Al_g = g_xl;
    const __nv_bfloat16* Bh_g = g_Wh + (size_t)which * (D_ * D_);
    const __nv_bfloat16* Bl_g = g_Wl + (size_t)which * (D_ * D_);
    float* C = which ? g_V : g_K;

    const int lrow = tid >> 1;          // 0..127
    const int lch  = tid & 1;           // half-row chunk (32B each)
    // global element offsets for cp.async (2 x 16B per part per thread)
    const size_t gA = (m0 + lrow) * D_ + lch * 16;
    const size_t gB = (size_t)(n0 + lrow) * D_ + lch * 16;
    // smem byte offsets
    const uint32_t sRow = (uint32_t)lrow * 80 + lch * 32;

    const int wm = (wid >> 2) * 64;
    const int wn = (wid & 3) * 32;
    const int g  = lane >> 2;
    const int t  = lane & 3;

    float c[4][4][4];
#pragma unroll
    for (int mi = 0; mi < 4; mi++)
#pragma unroll
        for (int ni = 0; ni < 4; ni++)
#pragma unroll
            for (int j = 0; j < 4; j++) c[mi][ni][j] = 0.f;

    auto stage = [&](int nb, int kt) {
        uint32_t bb = sb + (uint32_t)nb * BUF_WORDS * 4;
        int ke = kt * 32;
        cp16(bb + 0 * 10240 + sRow,      Ah_g + gA + ke);
        cp16(bb + 0 * 10240 + sRow + 16, Ah_g + gA + ke + 8);
        cp16(bb + 1 * 10240 + sRow,      Al_g + gA + ke);
        cp16(bb + 1 * 10240 + sRow + 16, Al_g + gA + ke + 8);
        cp16(bb + 2 * 10240 + sRow,      Bh_g + gB + ke);
        cp16(bb + 2 * 10240 + sRow + 16, Bh_g + gB + ke + 8);
        cp16(bb + 3 * 10240 + sRow,      Bl_g + gB + ke);
        cp16(bb + 3 * 10240 + sRow + 16, Bl_g + gB + ke + 8);
        cp_commit();
    };

    stage(0, 0);

    int buf = 0;
#pragma unroll 1
    for (int kt = 0; kt < 16; ++kt) {
        if (kt < 15) {
            stage(buf ^ 1, kt + 1);
            cp_wait<1>();
        } else {
            cp_wait<0>();
        }
        __syncthreads();

        const uint32_t* Ah = smw + buf * BUF_WORDS;
        const uint32_t* Al = Ah + TILE_WORDS;
        const uint32_t* Bh = Al + TILE_WORDS;
        const uint32_t* Bl = Bh + TILE_WORDS;

#pragma unroll
        for (int ks = 0; ks < 2; ks++) {
            const int ko = ks * 8 + t;
            uint32_t ah[4][4], bh[4][2];
#pragma unroll
            for (int mi = 0; mi < 4; mi++) {
                int w0 = (wm + mi * 16 + g) * GSTR + ko;
                ah[mi][0] = Ah[w0];
                ah[mi][1] = Ah[w0 + 8 * GSTR];
                ah[mi][2] = Ah[w0 + 4];
                ah[mi][3] = Ah[w0 + 8 * GSTR + 4];
            }
#pragma unroll
            for (int ni = 0; ni < 4; ni++) {
                int w0 = (wn + ni * 8 + g) * GSTR + ko;
                bh[ni][0] = Bh[w0];
                bh[ni][1] = Bh[w0 + 4];
            }
            // term 1: Ah * Bh
#pragma unroll
            for (int mi = 0; mi < 4; mi++)
#pragma unroll
                for (int ni = 0; ni < 4; ni++)
                    mma_bf16(c[mi][ni], ah[mi][0], ah[mi][1], ah[mi][2], ah[mi][3],
                             bh[ni][0], bh[ni][1]);
            // term 2: Ah * Bl
            uint32_t bl[4][2];
#pragma unroll
            for (int ni = 0; ni < 4; ni++) {
                int w0 = (wn + ni * 8 + g) * GSTR + ko;
                bl[ni][0] = Bl[w0];
                bl[ni][1] = Bl[w0 + 4];
            }
#pragma unroll
            for (int mi = 0; mi < 4; mi++)
#pragma unroll
                for (int ni = 0; ni < 4; ni++)
                    mma_bf16(c[mi][ni], ah[mi][0], ah[mi][1], ah[mi][2], ah[mi][3],
                             bl[ni][0], bl[ni][1]);
            // term 3: Al * Bh
#pragma unroll
            for (int mi = 0; mi < 4; mi++) {
                int w0 = (wm + mi * 16 + g) * GSTR + ko;
                uint32_t al0 = Al[w0];
                uint32_t al1 = Al[w0 + 8 * GSTR];
                uint32_t al2 = Al[w0 + 4];
                uint32_t al3 = Al[w0 + 8 * GSTR + 4];
#pragma unroll
                for (int ni = 0; ni < 4; ni++)
                    mma_bf16(c[mi][ni], al0, al1, al2, al3, bh[ni][0], bh[ni][1]);
            }
        }
        __syncthreads();
        buf ^= 1;
    }

#pragma unroll
    for (int mi = 0; mi < 4; mi++) {
#pragma unroll
        for (int ni = 0; ni < 4; ni++) {
            size_t r0 = m0 + wm + mi * 16 + g;
            int col = n0 + wn + ni * 8 + t * 2;
            *(float2*)&C[r0 * D_ + col]        = make_float2(c[mi][ni][0], c[mi][ni][1]);
            *(float2*)&C[(r0 + 8) * D_ + col]  = make_float2(c[mi][ni][2], c[mi][ni][3]);
        }
    }
}

// ---------------- 3. Qh: grid (P, H), 512 threads ----------------
__global__ __launch_bounds__(512) void qh_kernel(const float* __restrict__ proto,
                                                 const float* __restrict__ Wq) {
    __shared__ float pr[D_];
    __shared__ float qp[HD_];
    __shared__ float sinv;
    int p = blockIdx.x, h = blockIdx.y, tid = threadIdx.x;
    pr[tid] = proto[p * D_ + tid];
    __syncthreads();
    int nl = tid >> 2, part = tid & 3;
    const float* wr = Wq + (size_t)(h * HD_ + nl) * D_ + part * 128;
    const float* pp = pr + part * 128;
    float a = 0.f;
#pragma unroll 8
    for (int k = 0; k < 128; k += 4) {
        float4 w4 = *(const float4*)&wr[k];
        a += w4.x * pp[k] + w4.y * pp[k + 1] + w4.z * pp[k + 2] + w4.w * pp[k + 3];
    }
    a += __shfl_xor_sync(0xffffffffu, a, 1);
    a += __shfl_xor_sync(0xffffffffu, a, 2);
    if (part == 0) qp[nl] = a;
    __syncthreads();
    if (tid < 32) {
        float sq = 0.f;
#pragma unroll
        for (int j = 0; j < 4; j++) { float tv = qp[tid + 32 * j]; sq += tv * tv; }
#pragma unroll
        for (int o = 16; o > 0; o >>= 1) sq += __shfl_xor_sync(0xffffffffu, sq, o);
        if (tid == 0) sinv = 1.f / fmaxf(sqrtf(sq), 1e-12f);
    }
    __syncthreads();
    if (tid < HD_) g_Qh[(h * P_ + p) * HD_ + tid] = qp[tid] * sinv;
}

// ---------------- 4. attention partials (R4 scalar version) ----------------
__global__ __launch_bounds__(256) void att_kernel() {
    extern __shared__ float smf[];
    float* Qs = smf;
    float* Ss = smf + 3072;
    float* Vs = Ss + 12288;
    float* Ms = Vs + 8192;
    float* Ls = Ms + 24;
    int tid = threadIdx.x;
    int cz = blockIdx.x, h = blockIdx.y, b = blockIdx.z;

#pragma unroll
    for (int j = 0; j < 12; j++) {
        int i = tid + 256 * j;
        Qs[i] = g_Qh[h * (P_ * HD_) + i];
    }
    __syncthreads();

    for (int it = 0; it < 2; ++it) {
        int tl = tid + it * 256;
        const float4* kp = (const float4*)(g_K + ((size_t)(b * T_ + cz * CHUNK_ + tl)) * D_ + h * HD_);
        float acc[P_];
#pragma unroll
        for (int p = 0; p < P_; p++) acc[p] = 0.f;
        float nn = 0.f;
#pragma unroll 1
        for (int q = 0; q < 4; q++) {
            float kq[32];
#pragma unroll
            for (int i = 0; i < 8; i++) {
                float4 k4 = kp[q * 8 + i];
                kq[i * 4 + 0] = k4.x; kq[i * 4 + 1] = k4.y;
                kq[i * 4 + 2] = k4.z; kq[i * 4 + 3] = k4.w;
                nn += k4.x * k4.x + k4.y * k4.y + k4.z * k4.z + k4.w * k4.w;
            }
#pragma unroll
            for (int p = 0; p < P_; p++) {
                const float4* qr = (const float4*)&Qs[p * HD_ + q * 32];
                float a = 0.f;
#pragma unroll
                for (int i = 0; i < 8; i++) {
                    float4 q4 = qr[i];
                    a += q4.x * kq[i * 4] + q4.y * kq[i * 4 + 1] +
                         q4.z * kq[i * 4 + 2] + q4.w * kq[i * 4 + 3];
                }
                acc[p] += a;
            }
        }
        float inv = 1.f / (fmaxf(sqrtf(nn), 1e-12f) * 0.07f);
#pragma unroll
        for (int p = 0; p < P_; p++) Ss[p * CHUNK_ + tl] = acc[p] * inv;
    }
    __syncthreads();

    int w = tid >> 5, lane = tid & 31;
#pragma unroll 1
    for (int rr = 0; rr < 3; ++rr) {
        int p = w + rr * 8;
        float vals[16];
        float m = -3.4e38f;
#pragma unroll
        for (int j = 0; j < 16; j++) {
            vals[j] = Ss[p * CHUNK_ + lane + 32 * j];
            m = fmaxf(m, vals[j]);
        }
#pragma unroll
        for (int o = 16; o > 0; o >>= 1) m = fmaxf(m, __shfl_xor_sync(0xffffffffu, m, o));
        float s = 0.f;
#pragma unroll
        for (int j = 0; j < 16; j++) {
            float e = expf(vals[j] - m);
            Ss[p * CHUNK_ + lane + 32 * j] = e;
            s += e;
        }
#pragma unroll
        for (int o = 16; o > 0; o >>= 1) s += __shfl_xor_sync(0xffffffffu, s, o);
        if (lane == 0) { Ms[p] = m; Ls[p] = s; }
    }

    int pg = tid >> 6;
    int d2 = tid & 63;
    float2 acc6[6];
#pragma unroll
    for (int j = 0; j < 6; j++) acc6[j] = make_float2(0.f, 0.f);
    const float2* Vs2 = (const float2*)Vs;
#pragma unroll 1
    for (int st = 0; st < 8; ++st) {
        __syncthreads();
#pragma unroll
        for (int j = 0; j < 8; j++) {
            int lin = tid + 256 * j;
            int row = lin >> 5, c4 = lin & 31;
            float4 vv = *(const float4*)&g_V[((size_t)(b * T_ + cz * CHUNK_ + st * 64 + row)) * D_ + h * HD_ + c4 * 4];
            *(float4*)&Vs[row * HD_ + c4 * 4] = vv;
        }
        __syncthreads();
#pragma unroll 4
        for (int tt0 = 0; tt0 < 64; tt0++) {
            float2 v = Vs2[tt0 * 64 + d2];
            int tt = st * 64 + tt0;
#pragma unroll
            for (int j = 0; j < 6; j++) {
                float sv = Ss[(pg * 6 + j) * CHUNK_ + tt];
                acc6[j].x += sv * v.x;
                acc6[j].y += sv * v.y;
            }
        }
    }
    size_t pb = ((((size_t)b * H_ + h) * NC_ + cz) * P_) * 130;
#pragma unroll
    for (int j = 0; j < 6; j++) {
        int p = pg * 6 + j;
        float* dst = g_part + pb + (size_t)p * 130;
        *(float2*)&dst[2 + 2 * d2] = acc6[j];
        if (d2 == 0) { dst[0] = Ms[p]; dst[1] = Ls[p]; }
    }
}

// ---------------- 5. merge ----------------
__global__ __launch_bounds__(128) void merge_kernel() {
    int p = blockIdx.x, h = blockIdx.y, b = blockIdx.z;
    int d = threadIdx.x;
    float M = -3.4e38f;
    for (int c = 0; c < NC_; c++) {
        const float* pp = g_part + (((size_t)(b * H_ + h) * NC_ + c) * P_ + p) * 130;
        M = fmaxf(M, pp[0]);
    }
    float L = 0.f, val = 0.f;
    for (int c = 0; c < NC_; c++) {
        const float* pp = g_part + (((size_t)(b * H_ + h) * NC_ + c) * P_ + p) * 130;
        float wgt = expf(pp[0] - M);
        L   += pp[1] * wgt;
        val += pp[2 + d] * wgt;
    }
    float out = (L > 0.f) ? val / L : 0.f;
    g_pt[(b * P_ + p) * D_ + h * HD_ + d] = out;
}

// ---------------- 6. topk ----------------
__global__ __launch_bounds__(256) void topk_kernel() {
    int b = blockIdx.x, tid = threadIdx.x, w = tid >> 5, lane = tid & 31;
    __shared__ float ss[P_];
    __shared__ int idxs[TOPK_];
#pragma unroll 1
    for (int rr = 0; rr < 3; rr++) {
        int p = w + rr * 8;
        const float* pr = g_pt + (b * P_ + p) * D_;
        float sq = 0.f;
#pragma unroll
        for (int j = 0; j < 16; j++) { float tv = pr[lane + 32 * j]; sq += tv * tv; }
#pragma unroll
        for (int o = 16; o > 0; o >>= 1) sq += __shfl_xor_sync(0xffffffffu, sq, o);
        if (lane == 0) ss[p] = sq;
    }
    __syncthreads();
    if (tid == 0) {
        unsigned used = 0;
        for (int i = 0; i < TOPK_; i++) {
            int best = -1; float bv = -3.4e38f;
            for (int p = 0; p < P_; p++)
                if (!((used >> p) & 1) && ss[p] > bv) { bv = ss[p]; best = p; }
            used |= 1u << best;
            idxs[i] = best;
        }
    }
    __syncthreads();
    for (int d = tid; d < D_; d += 256) {
        float s = 0.f;
        for (int i = 0; i < TOPK_; i++) s += g_pt[(b * P_ + idxs[i]) * D_ + d];
        g_z[b * D_ + d] = s * (1.f / TOPK_);
    }
}

// ---------------- 7. MLP ----------------
__global__ __launch_bounds__(128) void mlp_kernel(int in_sel, const float* __restrict__ W,
                                                  const float* __restrict__ bias,
                                                  float* __restrict__ out_ext, int act) {
    __shared__ float zs[D_];
    int b = blockIdx.y, tid = threadIdx.x;
    int n = blockIdx.x * 128 + tid;
    const float* in = in_sel ? g_hid : g_z;
    for (int i = tid; i < D_; i += 128) zs[i] = in[b * D_ + i];
    __syncthreads();
    const float* wr = W + (size_t)n * D_;
    float s = bias[n];
    for (int k = 0; k < D_; k += 4) {
        float4 w4 = *(const float4*)&wr[k];
        s += w4.x * zs[k] + w4.y * zs[k + 1] + w4.z * zs[k + 2] + w4.w * zs[k + 3];
    }
    if (act) s = s / (1.f + expf(-s));
    float* out = out_ext ? out_ext : g_hid;
    out[b * D_ + n] = s;
}

// ---------------- launch ----------------
extern "C" void kernel_launch(void* const* d_in, const int* in_sizes, int n_in,
                              void* d_out, int out_size) {
    (void)in_sizes; (void)n_in; (void)out_size;
    const float* x     = (const float*)d_in[0];
    const float* proto = (const float*)d_in[1];
    const float* ln_g  = (const float*)d_in[2];
    const float* ln_b  = (const float*)d_in[3];
    const float* Wq    = (const float*)d_in[4];
    const float* Wk    = (const float*)d_in[5];
    const float* Wv    = (const float*)d_in[6];
    const float* W1    = (const float*)d_in[7];
    const float* b1    = (const float*)d_in[8];
    const float* W2    = (const float*)d_in[9];
    const float* b2    = (const float*)d_in[10];
    float* out = (float*)d_out;

    cudaFuncSetAttribute(gemm_bf16, cudaFuncAttributeMaxDynamicSharedMemorySize, GEMM_SMEM);
    cudaFuncSetAttribute(att_kernel, cudaFuncAttributeMaxDynamicSharedMemorySize, 94400);

    // order chosen so the ncu single-launch capture lands on gemm_bf16
    ln_kernel<<<(B_ * T_) / 8, 256>>>(x, ln_g, ln_b);
    round_w<<<(D_ * D_) / 256, 256>>>(Wk, Wv);
    qh_kernel<<<dim3(P_, H_), 512>>>(proto, Wq);
    gemm_bf16<<<dim3(8, 512), 256, GEMM_SMEM>>>();
    att_kernel<<<dim3(NC_, H_, B_), 256, 94400>>>();
    merge_kernel<<<dim3(P_, H_, B_), 128>>>();
    topk_kernel<<<B_, 256>>>();
    mlp_kernel<<<dim3(4, B_), 128>>>(0, W1, b1, nullptr, 1);
    mlp_kernel<<<dim3(4, B_), 128>>>(1, W2, b2, out, 0);
}

// round 7
// speedup vs baseline: 1.8540x; 1.6940x over previous
#include <cuda_runtime.h>
#include <cuda_fp16.h>
#include <cstdint>
#include <cstddef>

#define B_    8
#define T_    8192
#define D_    512
#define H_    4
#define P_    24
#define HD_   128
#define TOPK_ 12
#define NC_   16
#define CHUNK_ 512

// ---------------- scratch (static device globals; no allocation) ----------------
__device__ __align__(16) __half g_xh[(size_t)B_ * T_ * D_];   // xn (fp16)
__device__ __align__(16) __half g_Wh[2 * D_ * D_];            // Wk, Wv (fp16)
__device__ __align__(16) float g_K [(size_t)B_ * T_ * D_];
__device__ __align__(16) float g_V [(size_t)B_ * T_ * D_];
__device__ float g_Qh[H_ * P_ * HD_];
__device__ float g_part[(size_t)B_ * H_ * NC_ * P_ * 130];
__device__ float g_pt[B_ * P_ * D_];
__device__ float g_z [B_ * D_];
__device__ float g_hid[B_ * D_];

// ---------------- helpers ----------------
__device__ __forceinline__ uint32_t smem_u32(const void* p) {
    uint32_t a;
    asm("{ .reg .u64 t; cvta.to.shared.u64 t, %1; cvt.u32.u64 %0, t; }" : "=r"(a) : "l"(p));
    return a;
}
__device__ __forceinline__ void cp16(uint32_t s, const void* g) {
    asm volatile("cp.async.cg.shared.global [%0], [%1], 16;" :: "r"(s), "l"(g) : "memory");
}
__device__ __forceinline__ void cp_commit() {
    asm volatile("cp.async.commit_group;" ::: "memory");
}
template <int N> __device__ __forceinline__ void cp_wait() {
    asm volatile("cp.async.wait_group %0;" :: "n"(N) : "memory");
}
__device__ __forceinline__ void mma_f16(float* c,
                                        uint32_t a0, uint32_t a1, uint32_t a2, uint32_t a3,
                                        uint32_t b0, uint32_t b1) {
    asm volatile("mma.sync.aligned.m16n8k16.row.col.f32.f16.f16.f32 "
                 "{%0,%1,%2,%3}, {%4,%5,%6,%7}, {%8,%9}, {%0,%1,%2,%3};"
                 : "+f"(c[0]), "+f"(c[1]), "+f"(c[2]), "+f"(c[3])
                 : "r"(a0), "r"(a1), "r"(a2), "r"(a3), "r"(b0), "r"(b1));
}

// ---------------- 1. LayerNorm -> fp16 ----------------
__global__ __launch_bounds__(256) void ln_kernel(const float* __restrict__ x,
                                                 const float* __restrict__ gw,
                                                 const float* __restrict__ bw) {
    int lane = threadIdx.x & 31;
    size_t row = (size_t)blockIdx.x * 8 + (threadIdx.x >> 5);
    const float* xr = x + row * D_;
    float4 v[4];
    float s = 0.f, sq = 0.f;
#pragma unroll
    for (int j = 0; j < 4; j++) {
        v[j] = *(const float4*)&xr[lane * 4 + j * 128];
        s  += v[j].x + v[j].y + v[j].z + v[j].w;
        sq += v[j].x * v[j].x + v[j].y * v[j].y + v[j].z * v[j].z + v[j].w * v[j].w;
    }
#pragma unroll
    for (int o = 16; o > 0; o >>= 1) {
        s  += __shfl_xor_sync(0xffffffffu, s,  o);
        sq += __shfl_xor_sync(0xffffffffu, sq, o);
    }
    float mu   = s * (1.f / 512.f);
    float var  = sq * (1.f / 512.f) - mu * mu;
    float rstd = rsqrtf(var + 1e-5f);
#pragma unroll
    for (int j = 0; j < 4; j++) {
        int c = lane * 4 + j * 128;
        float4 gv = *(const float4*)&gw[c];
        float4 bv = *(const float4*)&bw[c];
        __half h[4];
        h[0] = __float2half_rn((v[j].x - mu) * rstd * gv.x + bv.x);
        h[1] = __float2half_rn((v[j].y - mu) * rstd * gv.y + bv.y);
        h[2] = __float2half_rn((v[j].z - mu) * rstd * gv.z + bv.z);
        h[3] = __float2half_rn((v[j].w - mu) * rstd * gv.w + bv.w);
        *(uint2*)&g_xh[row * D_ + c] = *(uint2*)h;
    }
}

// ---------------- 1b. W matrices -> fp16 ----------------
__global__ __launch_bounds__(256) void round_w(const float* __restrict__ Wk,
                                               const float* __restrict__ Wv) {
    int i = blockIdx.x * 256 + threadIdx.x;
    g_Wh[i]           = __float2half_rn(Wk[i]);
    g_Wh[D_ * D_ + i] = __float2half_rn(Wv[i]);
}

// ---------------- 2. fp16 mma GEMM: C = xn @ W^T ----------------
// grid (8, 512): x = which*4 + ntile, y = m tile. CTA 128x128, K in 16 chunks of 32.
// smem rows: 32 halves (64B) padded to 80B (20 words) -> conflict-free frag loads.
#define GSTR 20                    // words per row
#define TILE_WORDS (128 * GSTR)    // 2560 words = 10240 B per tile
#define BUF_WORDS  (2 * TILE_WORDS)
#define GEMM_SMEM  (2 * BUF_WORDS * 4)   // 40960 B

__global__ __launch_bounds__(256, 2) void gemm_f16() {
    extern __shared__ __align__(16) uint32_t smw[];
    const uint32_t sb = smem_u32(smw);

    const int tid = threadIdx.x;
    const int wid = tid >> 5, lane = tid & 31;
    const int which = blockIdx.x >> 2;
    const int n0 = (blockIdx.x & 3) * 128;
    const size_t m0 = (size_t)blockIdx.y * 128;

    const __half* A_g = g_xh;
    const __half* B_g = g_Wh + (size_t)which * (D_ * D_);
    float* C = which ? g_V : g_K;

    const int lrow = tid >> 1;          // 0..127
    const int lch  = tid & 1;           // half-row chunk (32B)
    const size_t gA = (m0 + lrow) * D_ + lch * 16;
    const size_t gB = (size_t)(n0 + lrow) * D_ + lch * 16;
    const uint32_t sRow = (uint32_t)lrow * 80 + lch * 32;

    const int wm = (wid >> 2) * 64;
    const int wn = (wid & 3) * 32;
    const int g  = lane >> 2;
    const int t  = lane & 3;

    float c[4][4][4];
#pragma unroll
    for (int mi = 0; mi < 4; mi++)
#pragma unroll
        for (int ni = 0; ni < 4; ni++)
#pragma unroll
            for (int j = 0; j < 4; j++) c[mi][ni][j] = 0.f;

    auto stage = [&](int nb, int kt) {
        uint32_t bb = sb + (uint32_t)nb * BUF_WORDS * 4;
        int ke = kt * 32;
        cp16(bb + sRow,               A_g + gA + ke);
        cp16(bb + sRow + 16,          A_g + gA + ke + 8);
        cp16(bb + 10240 + sRow,       B_g + gB + ke);
        cp16(bb + 10240 + sRow + 16,  B_g + gB + ke + 8);
        cp_commit();
    };

    stage(0, 0);

    int buf = 0;
#pragma unroll 1
    for (int kt = 0; kt < 16; ++kt) {
        if (kt < 15) {
            stage(buf ^ 1, kt + 1);
            cp_wait<1>();
        } else {
            cp_wait<0>();
        }
        __syncthreads();

        const uint32_t* As = smw + buf * BUF_WORDS;
        const uint32_t* Bs = As + TILE_WORDS;

#pragma unroll
        for (int ks = 0; ks < 2; ks++) {
            const int ko = ks * 8 + t;
            uint32_t a[4][4], bfr[4][2];
#pragma unroll
            for (int mi = 0; mi < 4; mi++) {
                int w0 = (wm + mi * 16 + g) * GSTR + ko;
                a[mi][0] = As[w0];
                a[mi][1] = As[w0 + 8 * GSTR];
                a[mi][2] = As[w0 + 4];
                a[mi][3] = As[w0 + 8 * GSTR + 4];
            }
#pragma unroll
            for (int ni = 0; ni < 4; ni++) {
                int w0 = (wn + ni * 8 + g) * GSTR + ko;
                bfr[ni][0] = Bs[w0];
                bfr[ni][1] = Bs[w0 + 4];
            }
#pragma unroll
            for (int mi = 0; mi < 4; mi++)
#pragma unroll
                for (int ni = 0; ni < 4; ni++)
                    mma_f16(c[mi][ni], a[mi][0], a[mi][1], a[mi][2], a[mi][3],
                            bfr[ni][0], bfr[ni][1]);
        }
        __syncthreads();
        buf ^= 1;
    }

#pragma unroll
    for (int mi = 0; mi < 4; mi++) {
#pragma unroll
        for (int ni = 0; ni < 4; ni++) {
            size_t r0 = m0 + wm + mi * 16 + g;
            int col = n0 + wn + ni * 8 + t * 2;
            *(float2*)&C[r0 * D_ + col]        = make_float2(c[mi][ni][0], c[mi][ni][1]);
            *(float2*)&C[(r0 + 8) * D_ + col]  = make_float2(c[mi][ni][2], c[mi][ni][3]);
        }
    }
}

// ---------------- 3. Qh: grid (P, H), 512 threads ----------------
__global__ __launch_bounds__(512) void qh_kernel(const float* __restrict__ proto,
                                                 const float* __restrict__ Wq) {
    __shared__ float pr[D_];
    __shared__ float qp[HD_];
    __shared__ float sinv;
    int p = blockIdx.x, h = blockIdx.y, tid = threadIdx.x;
    pr[tid] = proto[p * D_ + tid];
    __syncthreads();
    int nl = tid >> 2, part = tid & 3;
    const float* wr = Wq + (size_t)(h * HD_ + nl) * D_ + part * 128;
    const float* pp = pr + part * 128;
    float a = 0.f;
#pragma unroll 8
    for (int k = 0; k < 128; k += 4) {
        float4 w4 = *(const float4*)&wr[k];
        a += w4.x * pp[k] + w4.y * pp[k + 1] + w4.z * pp[k + 2] + w4.w * pp[k + 3];
    }
    a += __shfl_xor_sync(0xffffffffu, a, 1);
    a += __shfl_xor_sync(0xffffffffu, a, 2);
    if (part == 0) qp[nl] = a;
    __syncthreads();
    if (tid < 32) {
        float sq = 0.f;
#pragma unroll
        for (int j = 0; j < 4; j++) { float tv = qp[tid + 32 * j]; sq += tv * tv; }
#pragma unroll
        for (int o = 16; o > 0; o >>= 1) sq += __shfl_xor_sync(0xffffffffu, sq, o);
        if (tid == 0) sinv = 1.f / fmaxf(sqrtf(sq), 1e-12f);
    }
    __syncthreads();
    if (tid < HD_) g_Qh[(h * P_ + p) * HD_ + tid] = qp[tid] * sinv;
}

// ---------------- 4. attention partials (scalar, proven) ----------------
__global__ __launch_bounds__(256) void att_kernel() {
    extern __shared__ float smf[];
    float* Qs = smf;
    float* Ss = smf + 3072;
    float* Vs = Ss + 12288;
    float* Ms = Vs + 8192;
    float* Ls = Ms + 24;
    int tid = threadIdx.x;
    int cz = blockIdx.x, h = blockIdx.y, b = blockIdx.z;

#pragma unroll
    for (int j = 0; j < 12; j++) {
        int i = tid + 256 * j;
        Qs[i] = g_Qh[h * (P_ * HD_) + i];
    }
    __syncthreads();

    for (int it = 0; it < 2; ++it) {
        int tl = tid + it * 256;
        const float4* kp = (const float4*)(g_K + ((size_t)(b * T_ + cz * CHUNK_ + tl)) * D_ + h * HD_);
        float acc[P_];
#pragma unroll
        for (int p = 0; p < P_; p++) acc[p] = 0.f;
        float nn = 0.f;
#pragma unroll 1
        for (int q = 0; q < 4; q++) {
            float kq[32];
#pragma unroll
            for (int i = 0; i < 8; i++) {
                float4 k4 = kp[q * 8 + i];
                kq[i * 4 + 0] = k4.x; kq[i * 4 + 1] = k4.y;
                kq[i * 4 + 2] = k4.z; kq[i * 4 + 3] = k4.w;
                nn += k4.x * k4.x + k4.y * k4.y + k4.z * k4.z + k4.w * k4.w;
            }
#pragma unroll
            for (int p = 0; p < P_; p++) {
                const float4* qr = (const float4*)&Qs[p * HD_ + q * 32];
                float a = 0.f;
#pragma unroll
                for (int i = 0; i < 8; i++) {
                    float4 q4 = qr[i];
                    a += q4.x * kq[i * 4] + q4.y * kq[i * 4 + 1] +
                         q4.z * kq[i * 4 + 2] + q4.w * kq[i * 4 + 3];
                }
                acc[p] += a;
            }
        }
        float inv = 1.f / (fmaxf(sqrtf(nn), 1e-12f) * 0.07f);
#pragma unroll
        for (int p = 0; p < P_; p++) Ss[p * CHUNK_ + tl] = acc[p] * inv;
    }
    __syncthreads();

    int w = tid >> 5, lane = tid & 31;
#pragma unroll 1
    for (int rr = 0; rr < 3; ++rr) {
        int p = w + rr * 8;
        float vals[16];
        float m = -3.4e38f;
#pragma unroll
        for (int j = 0; j < 16; j++) {
            vals[j] = Ss[p * CHUNK_ + lane + 32 * j];
            m = fmaxf(m, vals[j]);
        }
#pragma unroll
        for (int o = 16; o > 0; o >>= 1) m = fmaxf(m, __shfl_xor_sync(0xffffffffu, m, o));
        float s = 0.f;
#pragma unroll
        for (int j = 0; j < 16; j++) {
            float e = expf(vals[j] - m);
            Ss[p * CHUNK_ + lane + 32 * j] = e;
            s += e;
        }
#pragma unroll
        for (int o = 16; o > 0; o >>= 1) s += __shfl_xor_sync(0xffffffffu, s, o);
        if (lane == 0) { Ms[p] = m; Ls[p] = s; }
    }

    int pg = tid >> 6;
    int d2 = tid & 63;
    float2 acc6[6];
#pragma unroll
    for (int j = 0; j < 6; j++) acc6[j] = make_float2(0.f, 0.f);
    const float2* Vs2 = (const float2*)Vs;
#pragma unroll 1
    for (int st = 0; st < 8; ++st) {
        __syncthreads();
#pragma unroll
        for (int j = 0; j < 8; j++) {
            int lin = tid + 256 * j;
            int row = lin >> 5, c4 = lin & 31;
            float4 vv = *(const float4*)&g_V[((size_t)(b * T_ + cz * CHUNK_ + st * 64 + row)) * D_ + h * HD_ + c4 * 4];
            *(float4*)&Vs[row * HD_ + c4 * 4] = vv;
        }
        __syncthreads();
#pragma unroll 4
        for (int tt0 = 0; tt0 < 64; tt0++) {
            float2 v = Vs2[tt0 * 64 + d2];
            int tt = st * 64 + tt0;
#pragma unroll
            for (int j = 0; j < 6; j++) {
                float sv = Ss[(pg * 6 + j) * CHUNK_ + tt];
                acc6[j].x += sv * v.x;
                acc6[j].y += sv * v.y;
            }
        }
    }
    size_t pb = ((((size_t)b * H_ + h) * NC_ + cz) * P_) * 130;
#pragma unroll
    for (int j = 0; j < 6; j++) {
        int p = pg * 6 + j;
        float* dst = g_part + pb + (size_t)p * 130;
        *(float2*)&dst[2 + 2 * d2] = acc6[j];
        if (d2 == 0) { dst[0] = Ms[p]; dst[1] = Ls[p]; }
    }
}

// ---------------- 5. merge ----------------
__global__ __launch_bounds__(128) void merge_kernel() {
    int p = blockIdx.x, h = blockIdx.y, b = blockIdx.z;
    int d = threadIdx.x;
    float M = -3.4e38f;
    for (int c = 0; c < NC_; c++) {
        const float* pp = g_part + (((size_t)(b * H_ + h) * NC_ + c) * P_ + p) * 130;
        M = fmaxf(M, pp[0]);
    }
    float L = 0.f, val = 0.f;
    for (int c = 0; c < NC_; c++) {
        const float* pp = g_part + (((size_t)(b * H_ + h) * NC_ + c) * P_ + p) * 130;
        float wgt = expf(pp[0] - M);
        L   += pp[1] * wgt;
        val += pp[2 + d] * wgt;
    }
    float out = (L > 0.f) ? val / L : 0.f;
    g_pt[(b * P_ + p) * D_ + h * HD_ + d] = out;
}

// ---------------- 6. topk ----------------
__global__ __launch_bounds__(256) void topk_kernel() {
    int b = blockIdx.x, tid = threadIdx.x, w = tid >> 5, lane = tid & 31;
    __shared__ float ss[P_];
    __shared__ int idxs[TOPK_];
#pragma unroll 1
    for (int rr = 0; rr < 3; rr++) {
        int p = w + rr * 8;
        const float* pr = g_pt + (b * P_ + p) * D_;
        float sq = 0.f;
#pragma unroll
        for (int j = 0; j < 16; j++) { float tv = pr[lane + 32 * j]; sq += tv * tv; }
#pragma unroll
        for (int o = 16; o > 0; o >>= 1) sq += __shfl_xor_sync(0xffffffffu, sq, o);
        if (lane == 0) ss[p] = sq;
    }
    __syncthreads();
    if (tid == 0) {
        unsigned used = 0;
        for (int i = 0; i < TOPK_; i++) {
            int best = -1; float bv = -3.4e38f;
            for (int p = 0; p < P_; p++)
                if (!((used >> p) & 1) && ss[p] > bv) { bv = ss[p]; best = p; }
            used |= 1u << best;
            idxs[i] = best;
        }
    }
    __syncthreads();
    for (int d = tid; d < D_; d += 256) {
        float s = 0.f;
        for (int i = 0; i < TOPK_; i++) s += g_pt[(b * P_ + idxs[i]) * D_ + d];
        g_z[b * D_ + d] = s * (1.f / TOPK_);
    }
}

// ---------------- 7. MLP ----------------
__global__ __launch_bounds__(128) void mlp_kernel(int in_sel, const float* __restrict__ W,
                                                  const float* __restrict__ bias,
                                                  float* __restrict__ out_ext, int act) {
    __shared__ float zs[D_];
    int b = blockIdx.y, tid = threadIdx.x;
    int n = blockIdx.x * 128 + tid;
    const float* in = in_sel ? g_hid : g_z;
    for (int i = tid; i < D_; i += 128) zs[i] = in[b * D_ + i];
    __syncthreads();
    const float* wr = W + (size_t)n * D_;
    float s = bias[n];
    for (int k = 0; k < D_; k += 4) {
        float4 w4 = *(const float4*)&wr[k];
        s += w4.x * zs[k] + w4.y * zs[k + 1] + w4.z * zs[k + 2] + w4.w * zs[k + 3];
    }
    if (act) s = s / (1.f + expf(-s));
    float* out = out_ext ? out_ext : g_hid;
    out[b * D_ + n] = s;
}

// ---------------- launch ----------------
extern "C" void kernel_launch(void* const* d_in, const int* in_sizes, int n_in,
                              void* d_out, int out_size) {
    (void)in_sizes; (void)n_in; (void)out_size;
    const float* x     = (const float*)d_in[0];
    const float* proto = (const float*)d_in[1];
    const float* ln_g  = (const float*)d_in[2];
    const float* ln_b  = (const float*)d_in[3];
    const float* Wq    = (const float*)d_in[4];
    const float* Wk    = (const float*)d_in[5];
    const float* Wv    = (const float*)d_in[6];
    const float* W1    = (const float*)d_in[7];
    const float* b1    = (const float*)d_in[8];
    const float* W2    = (const float*)d_in[9];
    const float* b2    = (const float*)d_in[10];
    float* out = (float*)d_out;

    cudaFuncSetAttribute(gemm_f16, cudaFuncAttributeMaxDynamicSharedMemorySize, GEMM_SMEM);
    cudaFuncSetAttribute(att_kernel, cudaFuncAttributeMaxDynamicSharedMemorySize, 94400);

    ln_kernel<<<(B_ * T_) / 8, 256>>>(x, ln_g, ln_b);
    round_w<<<(D_ * D_) / 256, 256>>>(Wk, Wv);
    qh_kernel<<<dim3(P_, H_), 512>>>(proto, Wq);
    gemm_f16<<<dim3(8, 512), 256, GEMM_SMEM>>>();
    att_kernel<<<dim3(NC_, H_, B_), 256, 94400>>>();
    merge_kernel<<<dim3(P_, H_, B_), 128>>>();
    topk_kernel<<<B_, 256>>>();
    mlp_kernel<<<dim3(4, B_), 128>>>(0, W1, b1, nullptr, 1);
    mlp_kernel<<<dim3(4, B_), 128>>>(1, W2, b2, out, 0);
}

// round 9
// speedup vs baseline: 1.9296x; 1.0408x over previous
#include <cuda_runtime.h>
#include <cuda_fp16.h>
#include <cstdint>
#include <cstddef>

#define B_    8
#define T_    8192
#define D_    512
#define H_    4
#define P_    24
#define HD_   128
#define TOPK_ 12
#define NC_   16
#define CHUNK_ 512

// ---------------- scratch (static device globals; no allocation) ----------------
__device__ __align__(16) __half g_xh[(size_t)B_ * T_ * D_];   // xn (fp16)
__device__ __align__(16) __half g_Wh[2 * D_ * D_];            // Wk, Wv (fp16)
__device__ __align__(16) __half g_K [(size_t)B_ * T_ * D_];   // K (fp16)
__device__ __align__(16) __half g_V [(size_t)B_ * T_ * D_];   // V (fp16)
__device__ float g_Qh[H_ * P_ * HD_];
__device__ float g_part[(size_t)B_ * H_ * NC_ * P_ * 130];
__device__ float g_pt[B_ * P_ * D_];
__device__ float g_z [B_ * D_];
__device__ float g_hid[B_ * D_];

// ---------------- helpers ----------------
__device__ __forceinline__ uint32_t smem_u32(const void* p) {
    uint32_t a;
    asm("{ .reg .u64 t; cvta.to.shared.u64 t, %1; cvt.u32.u64 %0, t; }" : "=r"(a) : "l"(p));
    return a;
}
__device__ __forceinline__ void cp16(uint32_t s, const void* g) {
    asm volatile("cp.async.cg.shared.global [%0], [%1], 16;" :: "r"(s), "l"(g) : "memory");
}
__device__ __forceinline__ void cp_commit() {
    asm volatile("cp.async.commit_group;" ::: "memory");
}
template <int N> __device__ __forceinline__ void cp_wait() {
    asm volatile("cp.async.wait_group %0;" :: "n"(N) : "memory");
}
__device__ __forceinline__ void ldsm4(uint32_t& r0, uint32_t& r1, uint32_t& r2, uint32_t& r3,
                                      uint32_t addr) {
    asm volatile("ldmatrix.sync.aligned.m8n8.x4.shared.b16 {%0,%1,%2,%3}, [%4];"
                 : "=r"(r0), "=r"(r1), "=r"(r2), "=r"(r3) : "r"(addr));
}
__device__ __forceinline__ void mma_f16(float* c,
                                        uint32_t a0, uint32_t a1, uint32_t a2, uint32_t a3,
                                        uint32_t b0, uint32_t b1) {
    asm volatile("mma.sync.aligned.m16n8k16.row.col.f32.f16.f16.f32 "
                 "{%0,%1,%2,%3}, {%4,%5,%6,%7}, {%8,%9}, {%0,%1,%2,%3};"
                 : "+f"(c[0]), "+f"(c[1]), "+f"(c[2]), "+f"(c[3])
                 : "r"(a0), "r"(a1), "r"(a2), "r"(a3), "r"(b0), "r"(b1));
}
// unpack uint4 (8 halves) into 8 floats, accumulate squared norm
__device__ __forceinline__ void h8_unpack(uint4 r, float* o, float& nn) {
    float2 f;
    f = __half22float2(*(__half2*)&r.x); o[0] = f.x; o[1] = f.y; nn += f.x * f.x + f.y * f.y;
    f = __half22float2(*(__half2*)&r.y); o[2] = f.x; o[3] = f.y; nn += f.x * f.x + f.y * f.y;
    f = __half22float2(*(__half2*)&r.z); o[4] = f.x; o[5] = f.y; nn += f.x * f.x + f.y * f.y;
    f = __half22float2(*(__half2*)&r.w); o[6] = f.x; o[7] = f.y; nn += f.x * f.x + f.y * f.y;
}

// ---------------- 1. LayerNorm -> fp16 ----------------
__global__ __launch_bounds__(256) void ln_kernel(const float* __restrict__ x,
                                                 const float* __restrict__ gw,
                                                 const float* __restrict__ bw) {
    int lane = threadIdx.x & 31;
    size_t row = (size_t)blockIdx.x * 8 + (threadIdx.x >> 5);
    const float* xr = x + row * D_;
    float4 v[4];
    float s = 0.f, sq = 0.f;
#pragma unroll
    for (int j = 0; j < 4; j++) {
        v[j] = *(const float4*)&xr[lane * 4 + j * 128];
        s  += v[j].x + v[j].y + v[j].z + v[j].w;
        sq += v[j].x * v[j].x + v[j].y * v[j].y + v[j].z * v[j].z + v[j].w * v[j].w;
    }
#pragma unroll
    for (int o = 16; o > 0; o >>= 1) {
        s  += __shfl_xor_sync(0xffffffffu, s,  o);
        sq += __shfl_xor_sync(0xffffffffu, sq, o);
    }
    float mu   = s * (1.f / 512.f);
    float var  = sq * (1.f / 512.f) - mu * mu;
    float rstd = rsqrtf(var + 1e-5f);
#pragma unroll
    for (int j = 0; j < 4; j++) {
        int c = lane * 4 + j * 128;
        float4 gv = *(const float4*)&gw[c];
        float4 bv = *(const float4*)&bw[c];
        __half h[4];
        h[0] = __float2half_rn((v[j].x - mu) * rstd * gv.x + bv.x);
        h[1] = __float2half_rn((v[j].y - mu) * rstd * gv.y + bv.y);
        h[2] = __float2half_rn((v[j].z - mu) * rstd * gv.z + bv.z);
        h[3] = __float2half_rn((v[j].w - mu) * rstd * gv.w + bv.w);
        *(uint2*)&g_xh[row * D_ + c] = *(uint2*)h;
    }
}

// ---------------- 1b. W matrices -> fp16 ----------------
__global__ __launch_bounds__(256) void round_w(const float* __restrict__ Wk,
                                               const float* __restrict__ Wv) {
    int i = blockIdx.x * 256 + threadIdx.x;
    g_Wh[i]           = __float2half_rn(Wk[i]);
    g_Wh[D_ * D_ + i] = __float2half_rn(Wv[i]);
}

// ---------------- 2. fp16 mma GEMM (ldmatrix + 3-stage pipeline) ----------------
// grid (8, 512). CTA 128x128, K in 16 chunks of 32. rows padded to 80 B.
#define ROWB 80
#define TILE_B (128 * ROWB)        // 10240 B per tile
#define STAGE_B (2 * TILE_B)       // A + B per stage
#define GEMM_SMEM (3 * STAGE_B)    // 61440 B

__global__ __launch_bounds__(256, 2) void gemm_f16() {
    extern __shared__ __align__(16) char smc[];
    const uint32_t sb = smem_u32(smc);

    const int tid = threadIdx.x;
    const int wid = tid >> 5, lane = tid & 31;
    const int which = blockIdx.x >> 2;
    const int n0 = (blockIdx.x & 3) * 128;
    const size_t m0 = (size_t)blockIdx.y * 128;

    const __half* A_g = g_xh;
    const __half* B_g = g_Wh + (size_t)which * (D_ * D_);
    __half* C = which ? g_V : g_K;

    const int lrow = tid >> 1;
    const int lch  = tid & 1;
    const size_t gA = (m0 + lrow) * D_ + lch * 16;
    const size_t gB = (size_t)(n0 + lrow) * D_ + lch * 16;
    const uint32_t sRow = (uint32_t)lrow * ROWB + lch * 32;

    const int wm = (wid >> 2) * 64;
    const int wn = (wid & 3) * 32;
    const int g  = lane >> 2;
    const int t  = lane & 3;

    // ldmatrix per-lane base offsets (bytes within tile)
    uint32_t aRow[4], bRow[2];
#pragma unroll
    for (int mi = 0; mi < 4; mi++)
        aRow[mi] = (uint32_t)(wm + mi * 16 + (lane & 15)) * ROWB + ((lane & 16) ? 16 : 0);
#pragma unroll
    for (int np = 0; np < 2; np++)
        bRow[np] = (uint32_t)(wn + np * 16 + ((lane & 16) ? 8 : 0) + (lane & 7)) * ROWB
                   + ((lane & 8) ? 16 : 0);

    float c[4][4][4];
#pragma unroll
    for (int mi = 0; mi < 4; mi++)
#pragma unroll
        for (int ni = 0; ni < 4; ni++)
#pragma unroll
            for (int j = 0; j < 4; j++) c[mi][ni][j] = 0.f;

    auto stage = [&](int st, int kt) {
        uint32_t bbA = sb + (uint32_t)st * STAGE_B;
        uint32_t bbB = bbA + TILE_B;
        int ke = kt * 32;
        cp16(bbA + sRow,      A_g + gA + ke);
        cp16(bbA + sRow + 16, A_g + gA + ke + 8);
        cp16(bbB + sRow,      B_g + gB + ke);
        cp16(bbB + sRow + 16, B_g + gB + ke + 8);
        cp_commit();
    };

    stage(0, 0);
    stage(1, 1);

#pragma unroll 1
    for (int kt = 0; kt < 16; ++kt) {
        if (kt < 15) cp_wait<1>(); else cp_wait<0>();
        __syncthreads();
        if (kt + 2 < 16) stage((kt + 2) % 3, kt + 2);

        const uint32_t bbA = sb + (uint32_t)(kt % 3) * STAGE_B;
        const uint32_t bbB = bbA + TILE_B;

#pragma unroll
        for (int ks = 0; ks < 2; ks++) {
            const uint32_t ko = ks * 32;
            uint32_t a[4][4], bq[2][4];
#pragma unroll
            for (int mi = 0; mi < 4; mi++)
                ldsm4(a[mi][0], a[mi][1], a[mi][2], a[mi][3], bbA + aRow[mi] + ko);
#pragma unroll
            for (int np = 0; np < 2; np++)
                ldsm4(bq[np][0], bq[np][1], bq[np][2], bq[np][3], bbB + bRow[np] + ko);
#pragma unroll
            for (int mi = 0; mi < 4; mi++)
#pragma unroll
                for (int np = 0; np < 2; np++) {
                    mma_f16(c[mi][np * 2],     a[mi][0], a[mi][1], a[mi][2], a[mi][3],
                            bq[np][0], bq[np][1]);
                    mma_f16(c[mi][np * 2 + 1], a[mi][0], a[mi][1], a[mi][2], a[mi][3],
                            bq[np][2], bq[np][3]);
                }
        }
    }

#pragma unroll
    for (int mi = 0; mi < 4; mi++) {
#pragma unroll
        for (int ni = 0; ni < 4; ni++) {
            size_t r0 = m0 + wm + mi * 16 + g;
            int col = n0 + wn + ni * 8 + t * 2;
            *(__half2*)&C[r0 * D_ + col]       = __floats2half2_rn(c[mi][ni][0], c[mi][ni][1]);
            *(__half2*)&C[(r0 + 8) * D_ + col] = __floats2half2_rn(c[mi][ni][2], c[mi][ni][3]);
        }
    }
}

// ---------------- 3. Qh: grid (P, H), 512 threads ----------------
__global__ __launch_bounds__(512) void qh_kernel(const float* __restrict__ proto,
                                                 const float* __restrict__ Wq) {
    __shared__ float pr[D_];
    __shared__ float qp[HD_];
    __shared__ float sinv;
    int p = blockIdx.x, h = blockIdx.y, tid = threadIdx.x;
    pr[tid] = proto[p * D_ + tid];
    __syncthreads();
    int nl = tid >> 2, part = tid & 3;
    const float* wr = Wq + (size_t)(h * HD_ + nl) * D_ + part * 128;
    const float* pp = pr + part * 128;
    float a = 0.f;
#pragma unroll 8
    for (int k = 0; k < 128; k += 4) {
        float4 w4 = *(const float4*)&wr[k];
        a += w4.x * pp[k] + w4.y * pp[k + 1] + w4.z * pp[k + 2] + w4.w * pp[k + 3];
    }
    a += __shfl_xor_sync(0xffffffffu, a, 1);
    a += __shfl_xor_sync(0xffffffffu, a, 2);
    if (part == 0) qp[nl] = a;
    __syncthreads();
    if (tid < 32) {
        float sq = 0.f;
#pragma unroll
        for (int j = 0; j < 4; j++) { float tv = qp[tid + 32 * j]; sq += tv * tv; }
#pragma unroll
        for (int o = 16; o > 0; o >>= 1) sq += __shfl_xor_sync(0xffffffffu, sq, o);
        if (tid == 0) sinv = 1.f / fmaxf(sqrtf(sq), 1e-12f);
    }
    __syncthreads();
    if (tid < HD_) g_Qh[(h * P_ + p) * HD_ + tid] = qp[tid] * sinv;
}

// ---------------- 4. attention partials (scalar; K/V fp16 in gmem) ----------------
__global__ __launch_bounds__(256) void att_kernel() {
    extern __shared__ float smf[];
    float* Qs = smf;
    float* Ss = smf + 3072;
    float* Vs = Ss + 12288;
    float* Ms = Vs + 8192;
    float* Ls = Ms + 24;
    int tid = threadIdx.x;
    int cz = blockIdx.x, h = blockIdx.y, b = blockIdx.z;

#pragma unroll
    for (int j = 0; j < 12; j++) {
        int i = tid + 256 * j;
        Qs[i] = g_Qh[h * (P_ * HD_) + i];
    }
    __syncthreads();

    for (int it = 0; it < 2; ++it) {
        int tl = tid + it * 256;
        const uint4* kp = (const uint4*)(g_K + ((size_t)(b * T_ + cz * CHUNK_ + tl)) * D_ + h * HD_);
        float acc[P_];
#pragma unroll
        for (int p = 0; p < P_; p++) acc[p] = 0.f;
        float nn = 0.f;
#pragma unroll 1
        for (int q = 0; q < 4; q++) {
            float kq[32];
#pragma unroll
            for (int i = 0; i < 4; i++) h8_unpack(kp[q * 4 + i], kq + i * 8, nn);
#pragma unroll
            for (int p = 0; p < P_; p++) {
                const float4* qr = (const float4*)&Qs[p * HD_ + q * 32];
                float a = 0.f;
#pragma unroll
                for (int i = 0; i < 8; i++) {
                    float4 q4 = qr[i];
                    a += q4.x * kq[i * 4] + q4.y * kq[i * 4 + 1] +
                         q4.z * kq[i * 4 + 2] + q4.w * kq[i * 4 + 3];
                }
                acc[p] += a;
            }
        }
        float inv = 1.f / (fmaxf(sqrtf(nn), 1e-12f) * 0.07f);
#pragma unroll
        for (int p = 0; p < P_; p++) Ss[p * CHUNK_ + tl] = acc[p] * inv;
    }
    __syncthreads();

    int w = tid >> 5, lane = tid & 31;
#pragma unroll 1
    for (int rr = 0; rr < 3; ++rr) {
        int p = w + rr * 8;
        float vals[16];
        float m = -3.4e38f;
#pragma unroll
        for (int j = 0; j < 16; j++) {
            vals[j] = Ss[p * CHUNK_ + lane + 32 * j];
            m = fmaxf(m, vals[j]);
        }
#pragma unroll
        for (int o = 16; o > 0; o >>= 1) m = fmaxf(m, __shfl_xor_sync(0xffffffffu, m, o));
        float s = 0.f;
#pragma unroll
        for (int j = 0; j < 16; j++) {
            float e = expf(vals[j] - m);
            Ss[p * CHUNK_ + lane + 32 * j] = e;
            s += e;
        }
#pragma unroll
        for (int o = 16; o > 0; o >>= 1) s += __shfl_xor_sync(0xffffffffu, s, o);
        if (lane == 0) { Ms[p] = m; Ls[p] = s; }
    }

    int pg = tid >> 6;
    int d2 = tid & 63;
    float2 acc6[6];
#pragma unroll
    for (int j = 0; j < 6; j++) acc6[j] = make_float2(0.f, 0.f);
    const float2* Vs2 = (const float2*)Vs;
#pragma unroll 1
    for (int st = 0; st < 8; ++st) {
        __syncthreads();
        // stage 64 tokens x 128 dims of V (fp16 gmem -> fp32 smem)
#pragma unroll
        for (int j = 0; j < 4; j++) {
            int lin = tid + 256 * j;          // 0..1023
            int row = lin >> 4, c8 = lin & 15;
            uint4 r = *(const uint4*)(g_V +
                ((size_t)(b * T_ + cz * CHUNK_ + st * 64 + row)) * D_ + h * HD_ + c8 * 8);
            float dummy = 0.f;
            float fv[8];
            h8_unpack(r, fv, dummy);
            *(float4*)&Vs[row * HD_ + c8 * 8]     = make_float4(fv[0], fv[1], fv[2], fv[3]);
            *(float4*)&Vs[row * HD_ + c8 * 8 + 4] = make_float4(fv[4], fv[5], fv[6], fv[7]);
        }
        __syncthreads();
#pragma unroll 4
        for (int tt0 = 0; tt0 < 64; tt0++) {
            float2 v = Vs2[tt0 * 64 + d2];
            int tt = st * 64 + tt0;
#pragma unroll
            for (int j = 0; j < 6; j++) {
                float sv = Ss[(pg * 6 + j) * CHUNK_ + tt];
                acc6[j].x += sv * v.x;
                acc6[j].y += sv * v.y;
            }
        }
    }
    size_t pb = ((((size_t)b * H_ + h) * NC_ + cz) * P_) * 130;
#pragma unroll
    for (int j = 0; j < 6; j++) {
        int p = pg * 6 + j;
        float* dst = g_part + pb + (size_t)p * 130;
        *(float2*)&dst[2 + 2 * d2] = acc6[j];
        if (d2 == 0) { dst[0] = Ms[p]; dst[1] = Ls[p]; }
    }
}

// ---------------- 5. merge ----------------
__global__ __launch_bounds__(128) void merge_kernel() {
    int p = blockIdx.x, h = blockIdx.y, b = blockIdx.z;
    int d = threadIdx.x;
    float M = -3.4e38f;
    for (int c = 0; c < NC_; c++) {
        const float* pp = g_part + (((size_t)(b * H_ + h) * NC_ + c) * P_ + p) * 130;
        M = fmaxf(M, pp[0]);
    }
    float L = 0.f, val = 0.f;
    for (int c = 0; c < NC_; c++) {
        const float* pp = g_part + (((size_t)(b * H_ + h) * NC_ + c) * P_ + p) * 130;
        float wgt = expf(pp[0] - M);
        L   += pp[1] * wgt;
        val += pp[2 + d] * wgt;
    }
    float out = (L > 0.f) ? val / L : 0.f;
    g_pt[(b * P_ + p) * D_ + h * HD_ + d] = out;
}

// ---------------- 6. topk ----------------
__global__ __launch_bounds__(256) void topk_kernel() {
    int b = blockIdx.x, tid = threadIdx.x, w = tid >> 5, lane = tid & 31;
    __shared__ float ss[P_];
    __shared__ int idxs[TOPK_];
#pragma unroll 1
    for (int rr = 0; rr < 3; rr++) {
        int p = w + rr * 8;
        const float* pr = g_pt + (b * P_ + p) * D_;
        float sq = 0.f;
#pragma unroll
        for (int j = 0; j < 16; j++) { float tv = pr[lane + 32 * j]; sq += tv * tv; }
#pragma unroll
        for (int o = 16; o > 0; o >>= 1) sq += __shfl_xor_sync(0xffffffffu, sq, o);
        if (lane == 0) ss[p] = sq;
    }
    __syncthreads();
    if (tid == 0) {
        unsigned used = 0;
        for (int i = 0; i < TOPK_; i++) {
            int best = -1; float bv = -3.4e38f;
            for (int p = 0; p < P_; p++)
                if (!((used >> p) & 1) && ss[p] > bv) { bv = ss[p]; best = p; }
            used |= 1u << best;
            idxs[i] = best;
        }
    }
    __syncthreads();
    for (int d = tid; d < D_; d += 256) {
        float s = 0.f;
        for (int i = 0; i < TOPK_; i++) s += g_pt[(b * P_ + idxs[i]) * D_ + d];
        g_z[b * D_ + d] = s * (1.f / TOPK_);
    }
}

// ---------------- 7. MLP ----------------
__global__ __launch_bounds__(128) void mlp_kernel(int in_sel, const float* __restrict__ W,
                                                  const float* __restrict__ bias,
                                                  float* __restrict__ out_ext, int act) {
    __shared__ float zs[D_];
    int b = blockIdx.y, tid = threadIdx.x;
    int n = blockIdx.x * 128 + tid;
    const float* in = in_sel ? g_hid : g_z;
    for (int i = tid; i < D_; i += 128) zs[i] = in[b * D_ + i];
    __syncthreads();
    const float* wr = W + (size_t)n * D_;
    float s = bias[n];
    for (int k = 0; k < D_; k += 4) {
        float4 w4 = *(const float4*)&wr[k];
        s += w4.x * zs[k] + w4.y * zs[k + 1] + w4.z * zs[k + 2] + w4.w * zs[k + 3];
    }
    if (act) s = s / (1.f + expf(-s));
    float* out = out_ext ? out_ext : g_hid;
    out[b * D_ + n] = s;
}

// ---------------- launch ----------------
extern "C" void kernel_launch(void* const* d_in, const int* in_sizes, int n_in,
                              void* d_out, int out_size) {
    (void)in_sizes; (void)n_in; (void)out_size;
    const float* x     = (const float*)d_in[0];
    const float* proto = (const float*)d_in[1];
    const float* ln_g  = (const float*)d_in[2];
    const float* ln_b  = (const float*)d_in[3];
    const float* Wq    = (const float*)d_in[4];
    const float* Wk    = (const float*)d_in[5];
    const float* Wv    = (const float*)d_in[6];
    const float* W1    = (const float*)d_in[7];
    const float* b1    = (const float*)d_in[8];
    const float* W2    = (const float*)d_in[9];
    const float* b2    = (const float*)d_in[10];
    float* out = (float*)d_out;

    cudaFuncSetAttribute(gemm_f16, cudaFuncAttributeMaxDynamicSharedMemorySize, GEMM_SMEM);
    cudaFuncSetAttribute(att_kernel, cudaFuncAttributeMaxDynamicSharedMemorySize, 94400);

    ln_kernel<<<(B_ * T_) / 8, 256>>>(x, ln_g, ln_b);
    round_w<<<(D_ * D_) / 256, 256>>>(Wk, Wv);
    qh_kernel<<<dim3(P_, H_), 512>>>(proto, Wq);
    gemm_f16<<<dim3(8, 512), 256, GEMM_SMEM>>>();
    att_kernel<<<dim3(NC_, H_, B_), 256, 94400>>>();
    merge_kernel<<<dim3(P_, H_, B_), 128>>>();
    topk_kernel<<<B_, 256>>>();
    mlp_kernel<<<dim3(4, B_), 128>>>(0, W1, b1, nullptr, 1);
    mlp_kernel<<<dim3(4, B_), 128>>>(1, W2, b2, out, 0);
}

// round 10
// speedup vs baseline: 2.3053x; 1.1947x over previous
#include <cuda_runtime.h>
#include <cuda_fp16.h>
#include <cstdint>
#include <cstddef>

#define B_    8
#define T_    8192
#define D_    512
#define H_    4
#define P_    24
#define HD_   128
#define TOPK_ 12
#define NC_   16
#define CHUNK_ 512

// ---------------- scratch (static device globals; no allocation) ----------------
__device__ __align__(16) __half g_xh[(size_t)B_ * T_ * D_];   // xn (fp16)
__device__ __align__(16) __half g_Wh[2 * D_ * D_];            // Wk, Wv (fp16)
__device__ __align__(16) __half g_K [(size_t)B_ * T_ * D_];   // K (fp16)
__device__ __align__(16) __half g_V [(size_t)B_ * T_ * D_];   // V (fp16)
__device__ float g_Qh[H_ * P_ * HD_];
__device__ float g_part[(size_t)B_ * H_ * NC_ * P_ * 130];
__device__ float g_pt[B_ * P_ * D_];
__device__ float g_z [B_ * D_];
__device__ float g_hid[B_ * D_];

// ---------------- helpers ----------------
__device__ __forceinline__ uint32_t smem_u32(const void* p) {
    uint32_t a;
    asm("{ .reg .u64 t; cvta.to.shared.u64 t, %1; cvt.u32.u64 %0, t; }" : "=r"(a) : "l"(p));
    return a;
}
__device__ __forceinline__ void cp16(uint32_t s, const void* g) {
    asm volatile("cp.async.cg.shared.global [%0], [%1], 16;" :: "r"(s), "l"(g) : "memory");
}
__device__ __forceinline__ void cp_commit() {
    asm volatile("cp.async.commit_group;" ::: "memory");
}
template <int N> __device__ __forceinline__ void cp_wait() {
    asm volatile("cp.async.wait_group %0;" :: "n"(N) : "memory");
}
__device__ __forceinline__ void ldsm4(uint32_t& r0, uint32_t& r1, uint32_t& r2, uint32_t& r3,
                                      uint32_t addr) {
    asm volatile("ldmatrix.sync.aligned.m8n8.x4.shared.b16 {%0,%1,%2,%3}, [%4];"
                 : "=r"(r0), "=r"(r1), "=r"(r2), "=r"(r3) : "r"(addr));
}
__device__ __forceinline__ void ldsm4t(uint32_t& r0, uint32_t& r1, uint32_t& r2, uint32_t& r3,
                                       uint32_t addr) {
    asm volatile("ldmatrix.sync.aligned.m8n8.x4.trans.shared.b16 {%0,%1,%2,%3}, [%4];"
                 : "=r"(r0), "=r"(r1), "=r"(r2), "=r"(r3) : "r"(addr));
}
__device__ __forceinline__ void mma_f16(float* c,
                                        uint32_t a0, uint32_t a1, uint32_t a2, uint32_t a3,
                                        uint32_t b0, uint32_t b1) {
    asm volatile("mma.sync.aligned.m16n8k16.row.col.f32.f16.f16.f32 "
                 "{%0,%1,%2,%3}, {%4,%5,%6,%7}, {%8,%9}, {%0,%1,%2,%3};"
                 : "+f"(c[0]), "+f"(c[1]), "+f"(c[2]), "+f"(c[3])
                 : "r"(a0), "r"(a1), "r"(a2), "r"(a3), "r"(b0), "r"(b1));
}
// unpack uint4 (8 halves) into 8 floats, accumulate squared norm
__device__ __forceinline__ void h8_unpack(uint4 r, float* o, float& nn) {
    float2 f;
    f = __half22float2(*(__half2*)&r.x); o[0] = f.x; o[1] = f.y; nn += f.x * f.x + f.y * f.y;
    f = __half22float2(*(__half2*)&r.y); o[2] = f.x; o[3] = f.y; nn += f.x * f.x + f.y * f.y;
    f = __half22float2(*(__half2*)&r.z); o[4] = f.x; o[5] = f.y; nn += f.x * f.x + f.y * f.y;
    f = __half22float2(*(__half2*)&r.w); o[6] = f.x; o[7] = f.y; nn += f.x * f.x + f.y * f.y;
}

// ---------------- 1. LayerNorm -> fp16 ----------------
__global__ __launch_bounds__(256) void ln_kernel(const float* __restrict__ x,
                                                 const float* __restrict__ gw,
                                                 const float* __restrict__ bw) {
    int lane = threadIdx.x & 31;
    size_t row = (size_t)blockIdx.x * 8 + (threadIdx.x >> 5);
    const float* xr = x + row * D_;
    float4 v[4];
    float s = 0.f, sq = 0.f;
#pragma unroll
    for (int j = 0; j < 4; j++) {
        v[j] = *(const float4*)&xr[lane * 4 + j * 128];
        s  += v[j].x + v[j].y + v[j].z + v[j].w;
        sq += v[j].x * v[j].x + v[j].y * v[j].y + v[j].z * v[j].z + v[j].w * v[j].w;
    }
#pragma unroll
    for (int o = 16; o > 0; o >>= 1) {
        s  += __shfl_xor_sync(0xffffffffu, s,  o);
        sq += __shfl_xor_sync(0xffffffffu, sq, o);
    }
    float mu   = s * (1.f / 512.f);
    float var  = sq * (1.f / 512.f) - mu * mu;
    float rstd = rsqrtf(var + 1e-5f);
#pragma unroll
    for (int j = 0; j < 4; j++) {
        int c = lane * 4 + j * 128;
        float4 gv = *(const float4*)&gw[c];
        float4 bv = *(const float4*)&bw[c];
        __half h[4];
        h[0] = __float2half_rn((v[j].x - mu) * rstd * gv.x + bv.x);
        h[1] = __float2half_rn((v[j].y - mu) * rstd * gv.y + bv.y);
        h[2] = __float2half_rn((v[j].z - mu) * rstd * gv.z + bv.z);
        h[3] = __float2half_rn((v[j].w - mu) * rstd * gv.w + bv.w);
        *(uint2*)&g_xh[row * D_ + c] = *(uint2*)h;
    }
}

// ---------------- 1b. W matrices -> fp16 ----------------
__global__ __launch_bounds__(256) void round_w(const float* __restrict__ Wk,
                                               const float* __restrict__ Wv) {
    int i = blockIdx.x * 256 + threadIdx.x;
    g_Wh[i]           = __float2half_rn(Wk[i]);
    g_Wh[D_ * D_ + i] = __float2half_rn(Wv[i]);
}

// ---------------- 2. fp16 mma GEMM (ldmatrix + 3-stage pipeline) ----------------
#define ROWB 80
#define TILE_B (128 * ROWB)
#define STAGE_B (2 * TILE_B)
#define GEMM_SMEM (3 * STAGE_B)    // 61440 B

__global__ __launch_bounds__(256, 2) void gemm_f16() {
    extern __shared__ __align__(16) char smc[];
    const uint32_t sb = smem_u32(smc);

    const int tid = threadIdx.x;
    const int wid = tid >> 5, lane = tid & 31;
    const int which = blockIdx.x >> 2;
    const int n0 = (blockIdx.x & 3) * 128;
    const size_t m0 = (size_t)blockIdx.y * 128;

    const __half* A_g = g_xh;
    const __half* B_g = g_Wh + (size_t)which * (D_ * D_);
    __half* C = which ? g_V : g_K;

    const int lrow = tid >> 1;
    const int lch  = tid & 1;
    const size_t gA = (m0 + lrow) * D_ + lch * 16;
    const size_t gB = (size_t)(n0 + lrow) * D_ + lch * 16;
    const uint32_t sRow = (uint32_t)lrow * ROWB + lch * 32;

    const int wm = (wid >> 2) * 64;
    const int wn = (wid & 3) * 32;
    const int g  = lane >> 2;
    const int t  = lane & 3;

    uint32_t aRow[4], bRow[2];
#pragma unroll
    for (int mi = 0; mi < 4; mi++)
        aRow[mi] = (uint32_t)(wm + mi * 16 + (lane & 15)) * ROWB + ((lane & 16) ? 16 : 0);
#pragma unroll
    for (int np = 0; np < 2; np++)
        bRow[np] = (uint32_t)(wn + np * 16 + ((lane & 16) ? 8 : 0) + (lane & 7)) * ROWB
                   + ((lane & 8) ? 16 : 0);

    float c[4][4][4];
#pragma unroll
    for (int mi = 0; mi < 4; mi++)
#pragma unroll
        for (int ni = 0; ni < 4; ni++)
#pragma unroll
            for (int j = 0; j < 4; j++) c[mi][ni][j] = 0.f;

    auto stage = [&](int st, int kt) {
        uint32_t bbA = sb + (uint32_t)st * STAGE_B;
        uint32_t bbB = bbA + TILE_B;
        int ke = kt * 32;
        cp16(bbA + sRow,      A_g + gA + ke);
        cp16(bbA + sRow + 16, A_g + gA + ke + 8);
        cp16(bbB + sRow,      B_g + gB + ke);
        cp16(bbB + sRow + 16, B_g + gB + ke + 8);
        cp_commit();
    };

    stage(0, 0);
    stage(1, 1);

#pragma unroll 1
    for (int kt = 0; kt < 16; ++kt) {
        if (kt < 15) cp_wait<1>(); else cp_wait<0>();
        __syncthreads();
        if (kt + 2 < 16) stage((kt + 2) % 3, kt + 2);

        const uint32_t bbA = sb + (uint32_t)(kt % 3) * STAGE_B;
        const uint32_t bbB = bbA + TILE_B;

#pragma unroll
        for (int ks = 0; ks < 2; ks++) {
            const uint32_t ko = ks * 32;
            uint32_t a[4][4], bq[2][4];
#pragma unroll
            for (int mi = 0; mi < 4; mi++)
                ldsm4(a[mi][0], a[mi][1], a[mi][2], a[mi][3], bbA + aRow[mi] + ko);
#pragma unroll
            for (int np = 0; np < 2; np++)
                ldsm4(bq[np][0], bq[np][1], bq[np][2], bq[np][3], bbB + bRow[np] + ko);
#pragma unroll
            for (int mi = 0; mi < 4; mi++)
#pragma unroll
                for (int np = 0; np < 2; np++) {
                    mma_f16(c[mi][np * 2],     a[mi][0], a[mi][1], a[mi][2], a[mi][3],
                            bq[np][0], bq[np][1]);
                    mma_f16(c[mi][np * 2 + 1], a[mi][0], a[mi][1], a[mi][2], a[mi][3],
                            bq[np][2], bq[np][3]);
                }
        }
    }

#pragma unroll
    for (int mi = 0; mi < 4; mi++) {
#pragma unroll
        for (int ni = 0; ni < 4; ni++) {
            size_t r0 = m0 + wm + mi * 16 + g;
            int col = n0 + wn + ni * 8 + t * 2;
            *(__half2*)&C[r0 * D_ + col]       = __floats2half2_rn(c[mi][ni][0], c[mi][ni][1]);
            *(__half2*)&C[(r0 + 8) * D_ + col] = __floats2half2_rn(c[mi][ni][2], c[mi][ni][3]);
        }
    }
}

// ---------------- 3. Qh: grid (P, H), 512 threads ----------------
__global__ __launch_bounds__(512) void qh_kernel(const float* __restrict__ proto,
                                                 const float* __restrict__ Wq) {
    __shared__ float pr[D_];
    __shared__ float qp[HD_];
    __shared__ float sinv;
    int p = blockIdx.x, h = blockIdx.y, tid = threadIdx.x;
    pr[tid] = proto[p * D_ + tid];
    __syncthreads();
    int nl = tid >> 2, part = tid & 3;
    const float* wr = Wq + (size_t)(h * HD_ + nl) * D_ + part * 128;
    const float* pp = pr + part * 128;
    float a = 0.f;
#pragma unroll 8
    for (int k = 0; k < 128; k += 4) {
        float4 w4 = *(const float4*)&wr[k];
        a += w4.x * pp[k] + w4.y * pp[k + 1] + w4.z * pp[k + 2] + w4.w * pp[k + 3];
    }
    a += __shfl_xor_sync(0xffffffffu, a, 1);
    a += __shfl_xor_sync(0xffffffffu, a, 2);
    if (part == 0) qp[nl] = a;
    __syncthreads();
    if (tid < 32) {
        float sq = 0.f;
#pragma unroll
        for (int j = 0; j < 4; j++) { float tv = qp[tid + 32 * j]; sq += tv * tv; }
#pragma unroll
        for (int o = 16; o > 0; o >>= 1) sq += __shfl_xor_sync(0xffffffffu, sq, o);
        if (tid == 0) sinv = 1.f / fmaxf(sqrtf(sq), 1e-12f);
    }
    __syncthreads();
    if (tid < HD_) g_Qh[(h * P_ + p) * HD_ + tid] = qp[tid] * sinv;
}

// ---------------- 4. attention via single-pass fp16 mma ----------------
// grid (NC, H, B), 256 threads. smem 180480 B.
// Layout (byte offsets): Q 32x136h @0; Kbuf 2x(128x136h) @8704; S fp32 32x520 @78336;
// P fp16 32x520 @144896; Nm 512f @178176; Ms 32f @180224; Ls 32f @180352.
#define oQ   0
#define oKB  8704
#define KBUF 34816
#define oS   78336
#define oP   144896
#define oNm  178176
#define oMs  180224
#define oLs  180352
#define ATT_SMEM 180480

__global__ __launch_bounds__(256) void att_mma() {
    extern __shared__ __align__(16) char smc[];
    const uint32_t sb = smem_u32(smc);
    __half* Qs = (__half*)(smc + oQ);
    float*  S  = (float*)(smc + oS);
    __half* P  = (__half*)(smc + oP);
    float*  Nm = (float*)(smc + oNm);
    float*  Ms = (float*)(smc + oMs);
    float*  Ls = (float*)(smc + oLs);
    const uint32_t* Qw = (const uint32_t*)Qs;
    const uint32_t* Pw = (const uint32_t*)P;

    const int tid = threadIdx.x;
    const int wid = tid >> 5, lane = tid & 31;
    const int g = lane >> 2, t = lane & 3;
    const int cz = blockIdx.x, h = blockIdx.y, b = blockIdx.z;
    const size_t tokbase = (size_t)(b * T_ + cz * CHUNK_);

    // Q: 32x128 (rows >= 24 zero), fp16, stride 136 halves
    for (int i = tid; i < 32 * 128; i += 256) {
        int p = i >> 7, d = i & 127;
        float v = (p < P_) ? g_Qh[(h * P_ + p) * HD_ + d] : 0.f;
        Qs[p * 136 + d] = __float2half_rn(v);
    }

    auto stageKV = [&](const __half* src, int st, int bf) {
        uint32_t bb = sb + oKB + (uint32_t)bf * KBUF;
#pragma unroll
        for (int j = 0; j < 8; j++) {
            int lin = tid + 256 * j;           // 0..2047
            int tok = lin >> 4, ch = lin & 15; // 16 x 16B chunks per 128-dim row
            cp16(bb + (uint32_t)(tok * 136 + ch * 8) * 2,
                 src + (tokbase + st * 128 + tok) * D_ + h * HD_ + ch * 8);
        }
        cp_commit();
    };

    stageKV(g_K, 0, 0);
    stageKV(g_K, 1, 1);

    // ================= scores =================
#pragma unroll 1
    for (int st = 0; st < 4; ++st) {
        cp_wait<1>();
        __syncthreads();
        const __half*   Kh = (const __half*)(smc + oKB + (st & 1) * KBUF);
        const uint32_t* Kw = (const uint32_t*)Kh;

        // per-token norms (2 threads/token)
        {
            int tok = tid >> 1, hf = tid & 1;
            const uint4* kp = (const uint4*)(Kh + tok * 136 + hf * 64);
            float nn = 0.f, tmp[8];
#pragma unroll
            for (int i = 0; i < 8; i++) h8_unpack(kp[i], tmp, nn);
            nn += __shfl_xor_sync(0xffffffffu, nn, 1);
            if (hf == 0) Nm[st * 128 + tok] = nn;
        }
        __syncthreads();

        float c[2][2][4] = {};
#pragma unroll
        for (int kt = 0; kt < 8; kt++) {
            uint32_t a[2][4];
#pragma unroll
            for (int mi = 0; mi < 2; mi++) {
                int base = (mi * 16 + g) * 68 + kt * 8 + t;
                a[mi][0] = Qw[base];
                a[mi][1] = Qw[base + 8 * 68];
                a[mi][2] = Qw[base + 4];
                a[mi][3] = Qw[base + 8 * 68 + 4];
            }
#pragma unroll
            for (int np = 0; np < 2; np++) {
                int tok = wid * 16 + np * 8 + g;
                int base = tok * 68 + kt * 8 + t;
                uint32_t b0 = Kw[base], b1 = Kw[base + 4];
#pragma unroll
                for (int mi = 0; mi < 2; mi++)
                    mma_f16(c[mi][np], a[mi][0], a[mi][1], a[mi][2], a[mi][3], b0, b1);
            }
        }
#pragma unroll
        for (int np = 0; np < 2; np++) {
            int tc = wid * 16 + np * 8 + t * 2;
            float inv0 = 1.f / (fmaxf(sqrtf(Nm[st * 128 + tc]),     1e-12f) * 0.07f);
            float inv1 = 1.f / (fmaxf(sqrtf(Nm[st * 128 + tc + 1]), 1e-12f) * 0.07f);
#pragma unroll
            for (int mi = 0; mi < 2; mi++) {
                int r0 = mi * 16 + g;
                S[r0 * 520 + st * 128 + tc]           = c[mi][np][0] * inv0;
                S[r0 * 520 + st * 128 + tc + 1]       = c[mi][np][1] * inv1;
                S[(r0 + 8) * 520 + st * 128 + tc]     = c[mi][np][2] * inv0;
                S[(r0 + 8) * 520 + st * 128 + tc + 1] = c[mi][np][3] * inv1;
            }
        }
        __syncthreads();
        if (st < 2) stageKV(g_K, st + 2, st & 1);   // K2, K3
        else        stageKV(g_V, st - 2, st & 1);   // V0, V1
    }

    // ================= softmax -> P (fp16); rows 24-31 benign =================
#pragma unroll 1
    for (int rr = 0; rr < 4; ++rr) {
        int p = wid + rr * 8;
        float vals[16];
        float m = -3.4e38f;
#pragma unroll
        for (int j = 0; j < 16; j++) {
            vals[j] = S[p * 520 + lane + 32 * j];
            m = fmaxf(m, vals[j]);
        }
#pragma unroll
        for (int o = 16; o > 0; o >>= 1) m = fmaxf(m, __shfl_xor_sync(0xffffffffu, m, o));
        float s = 0.f;
#pragma unroll
        for (int j = 0; j < 16; j++) {
            float e = expf(vals[j] - m);
            P[p * 520 + lane + 32 * j] = __float2half_rn(e);
            s += e;
        }
#pragma unroll
        for (int o = 16; o > 0; o >>= 1) s += __shfl_xor_sync(0xffffffffu, s, o);
        if (lane == 0) { Ms[p] = m; Ls[p] = s; }
    }

    // ================= PV =================
    float cp2[2][2][4] = {};
#pragma unroll 1
    for (int st = 0; st < 4; ++st) {
        if (st < 3) cp_wait<1>(); else cp_wait<0>();
        __syncthreads();
        uint32_t vb = sb + oKB + (uint32_t)(st & 1) * KBUF;

#pragma unroll
        for (int kt = 0; kt < 8; kt++) {
            uint32_t a[2][4];
#pragma unroll
            for (int mi = 0; mi < 2; mi++) {
                int base = (mi * 16 + g) * 260 + st * 64 + kt * 8 + t;
                a[mi][0] = Pw[base];
                a[mi][1] = Pw[base + 8 * 260];
                a[mi][2] = Pw[base + 4];
                a[mi][3] = Pw[base + 8 * 260 + 4];
            }
            // B = V^T frags via ldmatrix.x4.trans: rows = tokens, cols = dims
            uint32_t r0, r1, r2, r3;
            uint32_t addr = vb + (uint32_t)((kt * 16 + (lane & 15)) * 136 +
                                            wid * 16 + ((lane & 16) ? 8 : 0)) * 2;
            ldsm4t(r0, r1, r2, r3, addr);
#pragma unroll
            for (int mi = 0; mi < 2; mi++) {
                mma_f16(cp2[mi][0], a[mi][0], a[mi][1], a[mi][2], a[mi][3], r0, r1);
                mma_f16(cp2[mi][1], a[mi][0], a[mi][1], a[mi][2], a[mi][3], r2, r3);
            }
        }
        __syncthreads();
        if (st < 2) stageKV(g_V, st + 2, st & 1);   // V2, V3
    }

    // ---- write partials ----
    size_t base = (((size_t)(b * H_ + h) * NC_ + cz) * P_) * 130;
#pragma unroll
    for (int mi = 0; mi < 2; mi++)
#pragma unroll
        for (int np = 0; np < 2; np++)
#pragma unroll
            for (int j = 0; j < 4; j++) {
                int r = mi * 16 + g + ((j >> 1) ? 8 : 0);
                if (r < P_) {
                    int col = wid * 16 + np * 8 + t * 2 + (j & 1);
                    g_part[base + (size_t)r * 130 + 2 + col] = cp2[mi][np][j];
                }
            }
    if (tid < P_) {
        g_part[base + (size_t)tid * 130]     = Ms[tid];
        g_part[base + (size_t)tid * 130 + 1] = Ls[tid];
    }
}

// ---------------- 5. merge ----------------
__global__ __launch_bounds__(128) void merge_kernel() {
    int p = blockIdx.x, h = blockIdx.y, b = blockIdx.z;
    int d = threadIdx.x;
    float M = -3.4e38f;
    for (int c = 0; c < NC_; c++) {
        const float* pp = g_part + (((size_t)(b * H_ + h) * NC_ + c) * P_ + p) * 130;
        M = fmaxf(M, pp[0]);
    }
    float L = 0.f, val = 0.f;
    for (int c = 0; c < NC_; c++) {
        const float* pp = g_part + (((size_t)(b * H_ + h) * NC_ + c) * P_ + p) * 130;
        float wgt = expf(pp[0] - M);
        L   += pp[1] * wgt;
        val += pp[2 + d] * wgt;
    }
    float out = (L > 0.f) ? val / L : 0.f;
    g_pt[(b * P_ + p) * D_ + h * HD_ + d] = out;
}

// ---------------- 6. topk ----------------
__global__ __launch_bounds__(256) void topk_kernel() {
    int b = blockIdx.x, tid = threadIdx.x, w = tid >> 5, lane = tid & 31;
    __shared__ float ss[P_];
    __shared__ int idxs[TOPK_];
#pragma unroll 1
    for (int rr = 0; rr < 3; rr++) {
        int p = w + rr * 8;
        const float* pr = g_pt + (b * P_ + p) * D_;
        float sq = 0.f;
#pragma unroll
        for (int j = 0; j < 16; j++) { float tv = pr[lane + 32 * j]; sq += tv * tv; }
#pragma unroll
        for (int o = 16; o > 0; o >>= 1) sq += __shfl_xor_sync(0xffffffffu, sq, o);
        if (lane == 0) ss[p] = sq;
    }
    __syncthreads();
    if (tid == 0) {
        unsigned used = 0;
        for (int i = 0; i < TOPK_; i++) {
            int best = -1; float bv = -3.4e38f;
            for (int p = 0; p < P_; p++)
                if (!((used >> p) & 1) && ss[p] > bv) { bv = ss[p]; best = p; }
            used |= 1u << best;
            idxs[i] = best;
        }
    }
    __syncthreads();
    for (int d = tid; d < D_; d += 256) {
        float s = 0.f;
        for (int i = 0; i < TOPK_; i++) s += g_pt[(b * P_ + idxs[i]) * D_ + d];
        g_z[b * D_ + d] = s * (1.f / TOPK_);
    }
}

// ---------------- 7. MLP ----------------
__global__ __launch_bounds__(128) void mlp_kernel(int in_sel, const float* __restrict__ W,
                                                  const float* __restrict__ bias,
                                                  float* __restrict__ out_ext, int act) {
    __shared__ float zs[D_];
    int b = blockIdx.y, tid = threadIdx.x;
    int n = blockIdx.x * 128 + tid;
    const float* in = in_sel ? g_hid : g_z;
    for (int i = tid; i < D_; i += 128) zs[i] = in[b * D_ + i];
    __syncthreads();
    const float* wr = W + (size_t)n * D_;
    float s = bias[n];
    for (int k = 0; k < D_; k += 4) {
        float4 w4 = *(const float4*)&wr[k];
        s += w4.x * zs[k] + w4.y * zs[k + 1] + w4.z * zs[k + 2] + w4.w * zs[k + 3];
    }
    if (act) s = s / (1.f + expf(-s));
    float* out = out_ext ? out_ext : g_hid;
    out[b * D_ + n] = s;
}

// ---------------- launch ----------------
extern "C" void kernel_launch(void* const* d_in, const int* in_sizes, int n_in,
                              void* d_out, int out_size) {
    (void)in_sizes; (void)n_in; (void)out_size;
    const float* x     = (const float*)d_in[0];
    const float* proto = (const float*)d_in[1];
    const float* ln_g  = (const float*)d_in[2];
    const float* ln_b  = (const float*)d_in[3];
    const float* Wq    = (const float*)d_in[4];
    const float* Wk    = (const float*)d_in[5];
    const float* Wv    = (const float*)d_in[6];
    const float* W1    = (const float*)d_in[7];
    const float* b1    = (const float*)d_in[8];
    const float* W2    = (const float*)d_in[9];
    const float* b2    = (const float*)d_in[10];
    float* out = (float*)d_out;

    cudaFuncSetAttribute(gemm_f16, cudaFuncAttributeMaxDynamicSharedMemorySize, GEMM_SMEM);
    cudaFuncSetAttribute(att_mma, cudaFuncAttributeMaxDynamicSharedMemorySize, ATT_SMEM);

    ln_kernel<<<(B_ * T_) / 8, 256>>>(x, ln_g, ln_b);
    round_w<<<(D_ * D_) / 256, 256>>>(Wk, Wv);
    qh_kernel<<<dim3(P_, H_), 512>>>(proto, Wq);
    gemm_f16<<<dim3(8, 512), 256, GEMM_SMEM>>>();
    att_mma<<<dim3(NC_, H_, B_), 256, ATT_SMEM>>>();
    merge_kernel<<<dim3(P_, H_, B_), 128>>>();
    topk_kernel<<<B_, 256>>>();
    mlp_kernel<<<dim3(4, B_), 128>>>(0, W1, b1, nullptr, 1);
    mlp_kernel<<<dim3(4, B_), 128>>>(1, W2, b2, out, 0);
}

// round 12
// speedup vs baseline: 2.5921x; 1.1244x over previous
#include <cuda_runtime.h>
#include <cuda_fp16.h>
#include <cstdint>
#include <cstddef>

#define B_    8
#define T_    8192
#define D_    512
#define H_    4
#define P_    24
#define HD_   128
#define TOPK_ 12
#define NC_   16
#define CHUNK_ 512
#define PSTR  514   // per-proto partial stride: m, l, U[512]

// ---------------- scratch (static device globals; no allocation) ----------------
__device__ __align__(16) __half g_xh[(size_t)B_ * T_ * D_];   // xn (fp16)
__device__ __align__(16) __half g_Wh[2 * D_ * D_];            // Wk, Wv (fp16)
__device__ __align__(16) __half g_K [(size_t)B_ * T_ * D_];   // K (fp16)
__device__ float g_Qh[H_ * P_ * HD_];
__device__ float g_part[(size_t)B_ * H_ * NC_ * P_ * PSTR];
__device__ float g_U [(size_t)B_ * H_ * P_ * D_];
__device__ float g_pt[B_ * P_ * D_];
__device__ float g_z [B_ * D_];
__device__ float g_hid[B_ * D_];

// ---------------- helpers ----------------
__device__ __forceinline__ uint32_t smem_u32(const void* p) {
    uint32_t a;
    asm("{ .reg .u64 t; cvta.to.shared.u64 t, %1; cvt.u32.u64 %0, t; }" : "=r"(a) : "l"(p));
    return a;
}
__device__ __forceinline__ void cp16(uint32_t s, const void* g) {
    asm volatile("cp.async.cg.shared.global [%0], [%1], 16;" :: "r"(s), "l"(g) : "memory");
}
__device__ __forceinline__ void cp_commit() {
    asm volatile("cp.async.commit_group;" ::: "memory");
}
template <int N> __device__ __forceinline__ void cp_wait() {
    asm volatile("cp.async.wait_group %0;" :: "n"(N) : "memory");
}
__device__ __forceinline__ void ldsm4(uint32_t& r0, uint32_t& r1, uint32_t& r2, uint32_t& r3,
                                      uint32_t addr) {
    asm volatile("ldmatrix.sync.aligned.m8n8.x4.shared.b16 {%0,%1,%2,%3}, [%4];"
                 : "=r"(r0), "=r"(r1), "=r"(r2), "=r"(r3) : "r"(addr));
}
__device__ __forceinline__ void ldsm4t(uint32_t& r0, uint32_t& r1, uint32_t& r2, uint32_t& r3,
                                       uint32_t addr) {
    asm volatile("ldmatrix.sync.aligned.m8n8.x4.trans.shared.b16 {%0,%1,%2,%3}, [%4];"
                 : "=r"(r0), "=r"(r1), "=r"(r2), "=r"(r3) : "r"(addr));
}
__device__ __forceinline__ void mma_f16(float* c,
                                        uint32_t a0, uint32_t a1, uint32_t a2, uint32_t a3,
                                        uint32_t b0, uint32_t b1) {
    asm volatile("mma.sync.aligned.m16n8k16.row.col.f32.f16.f16.f32 "
                 "{%0,%1,%2,%3}, {%4,%5,%6,%7}, {%8,%9}, {%0,%1,%2,%3};"
                 : "+f"(c[0]), "+f"(c[1]), "+f"(c[2]), "+f"(c[3])
                 : "r"(a0), "r"(a1), "r"(a2), "r"(a3), "r"(b0), "r"(b1));
}
__device__ __forceinline__ void h8_unpack(uint4 r, float* o, float& nn) {
    float2 f;
    f = __half22float2(*(__half2*)&r.x); o[0] = f.x; o[1] = f.y; nn += f.x * f.x + f.y * f.y;
    f = __half22float2(*(__half2*)&r.y); o[2] = f.x; o[3] = f.y; nn += f.x * f.x + f.y * f.y;
    f = __half22float2(*(__half2*)&r.z); o[4] = f.x; o[5] = f.y; nn += f.x * f.x + f.y * f.y;
    f = __half22float2(*(__half2*)&r.w); o[6] = f.x; o[7] = f.y; nn += f.x * f.x + f.y * f.y;
}

// ---------------- 1. LayerNorm -> fp16 ----------------
__global__ __launch_bounds__(256) void ln_kernel(const float* __restrict__ x,
                                                 const float* __restrict__ gw,
                                                 const float* __restrict__ bw) {
    int lane = threadIdx.x & 31;
    size_t row = (size_t)blockIdx.x * 8 + (threadIdx.x >> 5);
    const float* xr = x + row * D_;
    float4 v[4];
    float s = 0.f, sq = 0.f;
#pragma unroll
    for (int j = 0; j < 4; j++) {
        v[j] = *(const float4*)&xr[lane * 4 + j * 128];
        s  += v[j].x + v[j].y + v[j].z + v[j].w;
        sq += v[j].x * v[j].x + v[j].y * v[j].y + v[j].z * v[j].z + v[j].w * v[j].w;
    }
#pragma unroll
    for (int o = 16; o > 0; o >>= 1) {
        s  += __shfl_xor_sync(0xffffffffu, s,  o);
        sq += __shfl_xor_sync(0xffffffffu, sq, o);
    }
    float mu   = s * (1.f / 512.f);
    float var  = sq * (1.f / 512.f) - mu * mu;
    float rstd = rsqrtf(var + 1e-5f);
#pragma unroll
    for (int j = 0; j < 4; j++) {
        int c = lane * 4 + j * 128;
        float4 gv = *(const float4*)&gw[c];
        float4 bv = *(const float4*)&bw[c];
        __half h[4];
        h[0] = __float2half_rn((v[j].x - mu) * rstd * gv.x + bv.x);
        h[1] = __float2half_rn((v[j].y - mu) * rstd * gv.y + bv.y);
        h[2] = __float2half_rn((v[j].z - mu) * rstd * gv.z + bv.z);
        h[3] = __float2half_rn((v[j].w - mu) * rstd * gv.w + bv.w);
        *(uint2*)&g_xh[row * D_ + c] = *(uint2*)h;
    }
}

// ---------------- 1b. W matrices -> fp16 ----------------
__global__ __launch_bounds__(256) void round_w(const float* __restrict__ Wk,
                                               const float* __restrict__ Wv) {
    int i = blockIdx.x * 256 + threadIdx.x;
    g_Wh[i]           = __float2half_rn(Wk[i]);
    g_Wh[D_ * D_ + i] = __float2half_rn(Wv[i]);
}

// ---------------- 2. fp16 mma GEMM: K = xn @ Wk^T (K projection ONLY) ----------------
#define ROWB 80
#define TILE_B (128 * ROWB)
#define STAGE_B (2 * TILE_B)
#define GEMM_SMEM (3 * STAGE_B)    // 61440 B

__global__ __launch_bounds__(256, 2) void gemm_f16() {
    extern __shared__ __align__(16) char smc[];
    const uint32_t sb = smem_u32(smc);

    const int tid = threadIdx.x;
    const int wid = tid >> 5, lane = tid & 31;
    const int n0 = blockIdx.x * 128;
    const size_t m0 = (size_t)blockIdx.y * 128;

    const __half* A_g = g_xh;
    const __half* B_g = g_Wh;           // Wk
    __half* C = g_K;

    const int lrow = tid >> 1;
    const int lch  = tid & 1;
    const size_t gA = (m0 + lrow) * D_ + lch * 16;
    const size_t gB = (size_t)(n0 + lrow) * D_ + lch * 16;
    const uint32_t sRow = (uint32_t)lrow * ROWB + lch * 32;

    const int wm = (wid >> 2) * 64;
    const int wn = (wid & 3) * 32;
    const int g  = lane >> 2;
    const int t  = lane & 3;

    uint32_t aRow[4], bRow[2];
#pragma unroll
    for (int mi = 0; mi < 4; mi++)
        aRow[mi] = (uint32_t)(wm + mi * 16 + (lane & 15)) * ROWB + ((lane & 16) ? 16 : 0);
#pragma unroll
    for (int np = 0; np < 2; np++)
        bRow[np] = (uint32_t)(wn + np * 16 + ((lane & 16) ? 8 : 0) + (lane & 7)) * ROWB
                   + ((lane & 8) ? 16 : 0);

    float c[4][4][4];
#pragma unroll
    for (int mi = 0; mi < 4; mi++)
#pragma unroll
        for (int ni = 0; ni < 4; ni++)
#pragma unroll
            for (int j = 0; j < 4; j++) c[mi][ni][j] = 0.f;

    auto stage = [&](int st, int kt) {
        uint32_t bbA = sb + (uint32_t)st * STAGE_B;
        uint32_t bbB = bbA + TILE_B;
        int ke = kt * 32;
        cp16(bbA + sRow,      A_g + gA + ke);
        cp16(bbA + sRow + 16, A_g + gA + ke + 8);
        cp16(bbB + sRow,      B_g + gB + ke);
        cp16(bbB + sRow + 16, B_g + gB + ke + 8);
        cp_commit();
    };

    stage(0, 0);
    stage(1, 1);

#pragma unroll 1
    for (int kt = 0; kt < 16; ++kt) {
        if (kt < 15) cp_wait<1>(); else cp_wait<0>();
        __syncthreads();
        if (kt + 2 < 16) stage((kt + 2) % 3, kt + 2);

        const uint32_t bbA = sb + (uint32_t)(kt % 3) * STAGE_B;
        const uint32_t bbB = bbA + TILE_B;

#pragma unroll
        for (int ks = 0; ks < 2; ks++) {
            const uint32_t ko = ks * 32;
            uint32_t a[4][4], bq[2][4];
#pragma unroll
            for (int mi = 0; mi < 4; mi++)
                ldsm4(a[mi][0], a[mi][1], a[mi][2], a[mi][3], bbA + aRow[mi] + ko);
#pragma unroll
            for (int np = 0; np < 2; np++)
                ldsm4(bq[np][0], bq[np][1], bq[np][2], bq[np][3], bbB + bRow[np] + ko);
#pragma unroll
            for (int mi = 0; mi < 4; mi++)
#pragma unroll
                for (int np = 0; np < 2; np++) {
                    mma_f16(c[mi][np * 2],     a[mi][0], a[mi][1], a[mi][2], a[mi][3],
                            bq[np][0], bq[np][1]);
                    mma_f16(c[mi][np * 2 + 1], a[mi][0], a[mi][1], a[mi][2], a[mi][3],
                            bq[np][2], bq[np][3]);
                }
        }
    }

#pragma unroll
    for (int mi = 0; mi < 4; mi++) {
#pragma unroll
        for (int ni = 0; ni < 4; ni++) {
            size_t r0 = m0 + wm + mi * 16 + g;
            int col = n0 + wn + ni * 8 + t * 2;
            *(__half2*)&C[r0 * D_ + col]       = __floats2half2_rn(c[mi][ni][0], c[mi][ni][1]);
            *(__half2*)&C[(r0 + 8) * D_ + col] = __floats2half2_rn(c[mi][ni][2], c[mi][ni][3]);
        }
    }
}

// ---------------- 3. Qh: grid (P, H), 512 threads ----------------
__global__ __launch_bounds__(512) void qh_kernel(const float* __restrict__ proto,
                                                 const float* __restrict__ Wq) {
    __shared__ float pr[D_];
    __shared__ float qp[HD_];
    __shared__ float sinv;
    int p = blockIdx.x, h = blockIdx.y, tid = threadIdx.x;
    pr[tid] = proto[p * D_ + tid];
    __syncthreads();
    int nl = tid >> 2, part = tid & 3;
    const float* wr = Wq + (size_t)(h * HD_ + nl) * D_ + part * 128;
    const float* pp = pr + part * 128;
    float a = 0.f;
#pragma unroll 8
    for (int k = 0; k < 128; k += 4) {
        float4 w4 = *(const float4*)&wr[k];
        a += w4.x * pp[k] + w4.y * pp[k + 1] + w4.z * pp[k + 2] + w4.w * pp[k + 3];
    }
    a += __shfl_xor_sync(0xffffffffu, a, 1);
    a += __shfl_xor_sync(0xffffffffu, a, 2);
    if (part == 0) qp[nl] = a;
    __syncthreads();
    if (tid < 32) {
        float sq = 0.f;
#pragma unroll
        for (int j = 0; j < 4; j++) { float tv = qp[tid + 32 * j]; sq += tv * tv; }
#pragma unroll
        for (int o = 16; o > 0; o >>= 1) sq += __shfl_xor_sync(0xffffffffu, sq, o);
        if (tid == 0) sinv = 1.f / fmaxf(sqrtf(sq), 1e-12f);
    }
    __syncthreads();
    if (tid < HD_) g_Qh[(h * P_ + p) * HD_ + tid] = qp[tid] * sinv;
}

// ---------------- 4. attention; PV against xn (U = attn @ xn) ----------------
// grid (H, NC, B), 256 threads. smem 180480 B.
#define oQ   0
#define oKB  8704
#define KBUF 34816
#define oS   78336
#define oP   144896
#define oNm  178176
#define oMs  180224
#define oLs  180352
#define ATT_SMEM 180480

__global__ __launch_bounds__(256) void att_mma() {
    extern __shared__ __align__(16) char smc[];
    const uint32_t sb = smem_u32(smc);
    __half* Qs = (__half*)(smc + oQ);
    float*  S  = (float*)(smc + oS);
    __half* P  = (__half*)(smc + oP);
    float*  Nm = (float*)(smc + oNm);
    float*  Ms = (float*)(smc + oMs);
    float*  Ls = (float*)(smc + oLs);
    const uint32_t* Qw = (const uint32_t*)Qs;
    const uint32_t* Pw = (const uint32_t*)P;

    const int tid = threadIdx.x;
    const int wid = tid >> 5, lane = tid & 31;
    const int g = lane >> 2, t = lane & 3;
    const int h = blockIdx.x, cz = blockIdx.y, b = blockIdx.z;
    const size_t tokbase = (size_t)(b * T_ + cz * CHUNK_);

    for (int i = tid; i < 32 * 128; i += 256) {
        int p = i >> 7, d = i & 127;
        float v = (p < P_) ? g_Qh[(h * P_ + p) * HD_ + d] : 0.f;
        Qs[p * 136 + d] = __float2half_rn(v);
    }

    // K sub-tile stage (head slice)
    auto stageK = [&](int st, int bf) {
        uint32_t bb = sb + oKB + (uint32_t)bf * KBUF;
#pragma unroll
        for (int j = 0; j < 8; j++) {
            int lin = tid + 256 * j;
            int tok = lin >> 4, ch = lin & 15;
            cp16(bb + (uint32_t)(tok * 136 + ch * 8) * 2,
                 g_K + (tokbase + st * 128 + tok) * D_ + h * HD_ + ch * 8);
        }
        cp_commit();
    };
    // xn sub-tile stage (dgroup slice of full 512 dims)
    auto stageXN = [&](int dg, int st, int bf) {
        uint32_t bb = sb + oKB + (uint32_t)bf * KBUF;
#pragma unroll
        for (int j = 0; j < 8; j++) {
            int lin = tid + 256 * j;
            int tok = lin >> 4, ch = lin & 15;
            cp16(bb + (uint32_t)(tok * 136 + ch * 8) * 2,
                 g_xh + (tokbase + st * 128 + tok) * D_ + dg * 128 + ch * 8);
        }
        cp_commit();
    };

    stageK(0, 0);
    stageK(1, 1);

    // ================= scores =================
#pragma unroll 1
    for (int st = 0; st < 4; ++st) {
        cp_wait<1>();
        __syncthreads();
        const __half*   Kh = (const __half*)(smc + oKB + (st & 1) * KBUF);
        const uint32_t* Kw = (const uint32_t*)Kh;

        {
            int tok = tid >> 1, hf = tid & 1;
            const uint4* kp = (const uint4*)(Kh + tok * 136 + hf * 64);
            float nn = 0.f, tmp[8];
#pragma unroll
            for (int i = 0; i < 8; i++) h8_unpack(kp[i], tmp, nn);
            nn += __shfl_xor_sync(0xffffffffu, nn, 1);
            if (hf == 0) Nm[st * 128 + tok] = nn;
        }
        __syncthreads();

        float c[2][2][4] = {};
#pragma unroll
        for (int kt = 0; kt < 8; kt++) {
            uint32_t a[2][4];
#pragma unroll
            for (int mi = 0; mi < 2; mi++) {
                int base = (mi * 16 + g) * 68 + kt * 8 + t;
                a[mi][0] = Qw[base];
                a[mi][1] = Qw[base + 8 * 68];
                a[mi][2] = Qw[base + 4];
                a[mi][3] = Qw[base + 8 * 68 + 4];
            }
#pragma unroll
            for (int np = 0; np < 2; np++) {
                int tok = wid * 16 + np * 8 + g;
                int base = tok * 68 + kt * 8 + t;
                uint32_t b0 = Kw[base], b1 = Kw[base + 4];
#pragma unroll
                for (int mi = 0; mi < 2; mi++)
                    mma_f16(c[mi][np], a[mi][0], a[mi][1], a[mi][2], a[mi][3], b0, b1);
            }
        }
#pragma unroll
        for (int np = 0; np < 2; np++) {
            int tc = wid * 16 + np * 8 + t * 2;
            float inv0 = 1.f / (fmaxf(sqrtf(Nm[st * 128 + tc]),     1e-12f) * 0.07f);
            float inv1 = 1.f / (fmaxf(sqrtf(Nm[st * 128 + tc + 1]), 1e-12f) * 0.07f);
#pragma unroll
            for (int mi = 0; mi < 2; mi++) {
                int r0 = mi * 16 + g;
                S[r0 * 520 + st * 128 + tc]           = c[mi][np][0] * inv0;
                S[r0 * 520 + st * 128 + tc + 1]       = c[mi][np][1] * inv1;
                S[(r0 + 8) * 520 + st * 128 + tc]     = c[mi][np][2] * inv0;
                S[(r0 + 8) * 520 + st * 128 + tc + 1] = c[mi][np][3] * inv1;
            }
        }
        __syncthreads();
        if (st < 2) stageK(st + 2, st & 1);
        else        stageXN(0, st - 2, st & 1);   // PV stages ls=0,1
    }

    // ================= softmax -> P fp16 (rows 24-31 benign) =================
#pragma unroll 1
    for (int rr = 0; rr < 4; ++rr) {
        int p = wid + rr * 8;
        float vals[16];
        float m = -3.4e38f;
#pragma unroll
        for (int j = 0; j < 16; j++) {
            vals[j] = S[p * 520 + lane + 32 * j];
            m = fmaxf(m, vals[j]);
        }
#pragma unroll
        for (int o = 16; o > 0; o >>= 1) m = fmaxf(m, __shfl_xor_sync(0xffffffffu, m, o));
        float s = 0.f;
#pragma unroll
        for (int j = 0; j < 16; j++) {
            float e = expf(vals[j] - m);
            P[p * 520 + lane + 32 * j] = __float2half_rn(e);
            s += e;
        }
#pragma unroll
        for (int o = 16; o > 0; o >>= 1) s += __shfl_xor_sync(0xffffffffu, s, o);
        if (lane == 0) { Ms[p] = m; Ls[p] = s; }
    }

    // ================= PV: U = P @ xn, 4 dgroups x 4 token sub-tiles =================
    size_t base = (((size_t)(b * H_ + h) * NC_ + cz) * P_) * PSTR;
    float cp2[2][2][4] = {};
#pragma unroll 1
    for (int ls = 0; ls < 16; ++ls) {
        int dg = ls >> 2, st = ls & 3;
        if (ls < 15) cp_wait<1>(); else cp_wait<0>();
        __syncthreads();
        uint32_t vb = sb + oKB + (uint32_t)(ls & 1) * KBUF;

#pragma unroll
        for (int kt = 0; kt < 8; kt++) {
            uint32_t a[2][4];
#pragma unroll
            for (int mi = 0; mi < 2; mi++) {
                int abase = (mi * 16 + g) * 260 + st * 64 + kt * 8 + t;
                a[mi][0] = Pw[abase];
                a[mi][1] = Pw[abase + 8 * 260];
                a[mi][2] = Pw[abase + 4];
                a[mi][3] = Pw[abase + 8 * 260 + 4];
            }
            uint32_t r0, r1, r2, r3;
            uint32_t addr = vb + (uint32_t)((kt * 16 + (lane & 15)) * 136 +
                                            wid * 16 + ((lane & 16) ? 8 : 0)) * 2;
            ldsm4t(r0, r1, r2, r3, addr);
#pragma unroll
            for (int mi = 0; mi < 2; mi++) {
                mma_f16(cp2[mi][0], a[mi][0], a[mi][1], a[mi][2], a[mi][3], r0, r1);
                mma_f16(cp2[mi][1], a[mi][0], a[mi][1], a[mi][2], a[mi][3], r2, r3);
            }
        }
        __syncthreads();
        if (ls + 2 < 16) stageXN((ls + 2) >> 2, (ls + 2) & 3, ls & 1);

        if (st == 3) {
            // write U partial slice for this dgroup, reset accumulators
#pragma unroll
            for (int mi = 0; mi < 2; mi++)
#pragma unroll
                for (int np = 0; np < 2; np++)
#pragma unroll
                    for (int j = 0; j < 4; j++) {
                        int r = mi * 16 + g + ((j >> 1) ? 8 : 0);
                        if (r < P_) {
                            int col = dg * 128 + wid * 16 + np * 8 + t * 2 + (j & 1);
                            g_part[base + (size_t)r * PSTR + 2 + col] = cp2[mi][np][j];
                        }
                        cp2[mi][np][j] = 0.f;
                    }
        }
    }
    if (tid < P_) {
        g_part[base + (size_t)tid * PSTR]     = Ms[tid];
        g_part[base + (size_t)tid * PSTR + 1] = Ls[tid];
    }
}

// ---------------- 5. merge chunk partials -> U (already /L) ----------------
__global__ __launch_bounds__(512) void merge_kernel() {
    int p = blockIdx.x, h = blockIdx.y, b = blockIdx.z;
    int d = threadIdx.x;
    float M = -3.4e38f;
    for (int c = 0; c < NC_; c++) {
        const float* pp = g_part + (((size_t)(b * H_ + h) * NC_ + c) * P_ + p) * PSTR;
        M = fmaxf(M, pp[0]);
    }
    float L = 0.f, val = 0.f;
    for (int c = 0; c < NC_; c++) {
        const float* pp = g_part + (((size_t)(b * H_ + h) * NC_ + c) * P_ + p) * PSTR;
        float wgt = expf(pp[0] - M);
        L   += pp[1] * wgt;
        val += pp[2 + d] * wgt;
    }
    float out = (L > 0.f) ? val / L : 0.f;
    g_U[(((size_t)b * H_ + h) * P_ + p) * D_ + d] = out;
}

// ---------------- 5b. project: proto_tokens = U @ Wv_h^T ----------------
__global__ __launch_bounds__(512) void proj_kernel() {
    __shared__ float Us[H_ * D_];
    int p = blockIdx.x, b = blockIdx.y, tid = threadIdx.x;
    for (int i = tid; i < H_ * D_; i += 512) {
        int h = i >> 9, k = i & 511;
        Us[i] = g_U[(((size_t)b * H_ + h) * P_ + p) * D_ + k];
    }
    __syncthreads();
    int h = tid >> 7, dd = tid & 127;
    const __half* wr = g_Wh + (size_t)D_ * D_ + (size_t)(h * HD_ + dd) * D_;  // Wv row
    const float* u = Us + h * D_;
    float s = 0.f;
#pragma unroll 8
    for (int k = 0; k < D_; k += 8) {
        uint4 r = *(const uint4*)(wr + k);
        float w[8], dmy = 0.f;
        h8_unpack(r, w, dmy);
        s += w[0] * u[k]     + w[1] * u[k + 1] + w[2] * u[k + 2] + w[3] * u[k + 3]
           + w[4] * u[k + 4] + w[5] * u[k + 5] + w[6] * u[k + 6] + w[7] * u[k + 7];
    }
    g_pt[(b * P_ + p) * D_ + h * HD_ + dd] = s;
}

// ---------------- 6. topk ----------------
__global__ __launch_bounds__(256) void topk_kernel() {
    int b = blockIdx.x, tid = threadIdx.x, w = tid >> 5, lane = tid & 31;
    __shared__ float ss[P_];
    __shared__ int idxs[TOPK_];
#pragma unroll 1
    for (int rr = 0; rr < 3; rr++) {
        int p = w + rr * 8;
        const float* pr = g_pt + (b * P_ + p) * D_;
        float sq = 0.f;
#pragma unroll
        for (int j = 0; j < 16; j++) { float tv = pr[lane + 32 * j]; sq += tv * tv; }
#pragma unroll
        for (int o = 16; o > 0; o >>= 1) sq += __shfl_xor_sync(0xffffffffu, sq, o);
        if (lane == 0) ss[p] = sq;
    }
    __syncthreads();
    if (tid == 0) {
        unsigned used = 0;
        for (int i = 0; i < TOPK_; i++) {
            int best = -1; float bv = -3.4e38f;
            for (int p = 0; p < P_; p++)
                if (!((used >> p) & 1) && ss[p] > bv) { bv = ss[p]; best = p; }
            used |= 1u << best;
            idxs[i] = best;
        }
    }
    __syncthreads();
    for (int d = tid; d < D_; d += 256) {
        float s = 0.f;
        for (int i = 0; i < TOPK_; i++) s += g_pt[(b * P_ + idxs[i]) * D_ + d];
        g_z[b * D_ + d] = s * (1.f / TOPK_);
    }
}

// ---------------- 7. MLP ----------------
__global__ __launch_bounds__(128) void mlp_kernel(int in_sel, const float* __restrict__ W,
                                                  const float* __restrict__ bias,
                                                  float* __restrict__ out_ext, int act) {
    __shared__ float zs[D_];
    int b = blockIdx.y, tid = threadIdx.x;
    int n = blockIdx.x * 128 + tid;
    const float* in = in_sel ? g_hid : g_z;
    for (int i = tid; i < D_; i += 128) zs[i] = in[b * D_ + i];
    __syncthreads();
    const float* wr = W + (size_t)n * D_;
    float s = bias[n];
    for (int k = 0; k < D_; k += 4) {
        float4 w4 = *(const float4*)&wr[k];
        s += w4.x * zs[k] + w4.y * zs[k + 1] + w4.z * zs[k + 2] + w4.w * zs[k + 3];
    }
    if (act) s = s / (1.f + expf(-s));
    float* out = out_ext ? out_ext : g_hid;
    out[b * D_ + n] = s;
}

// ---------------- launch ----------------
extern "C" void kernel_launch(void* const* d_in, const int* in_sizes, int n_in,
                              void* d_out, int out_size) {
    (void)in_sizes; (void)n_in; (void)out_size;
    const float* x     = (const float*)d_in[0];
    const float* proto = (const float*)d_in[1];
    const float* ln_g  = (const float*)d_in[2];
    const float* ln_b  = (const float*)d_in[3];
    const float* Wq    = (const float*)d_in[4];
    const float* Wk    = (const float*)d_in[5];
    const float* Wv    = (const float*)d_in[6];
    const float* W1    = (const float*)d_in[7];
    const float* b1    = (const float*)d_in[8];
    const float* W2    = (const float*)d_in[9];
    const float* b2    = (const float*)d_in[10];
    float* out = (float*)d_out;

    cudaFuncSetAttribute(gemm_f16, cudaFuncAttributeMaxDynamicSharedMemorySize, GEMM_SMEM);
    cudaFuncSetAttribute(att_mma, cudaFuncAttributeMaxDynamicSharedMemorySize, ATT_SMEM);

    ln_kernel<<<(B_ * T_) / 8, 256>>>(x, ln_g, ln_b);
    round_w<<<(D_ * D_) / 256, 256>>>(Wk, Wv);
    qh_kernel<<<dim3(P_, H_), 512>>>(proto, Wq);
    gemm_f16<<<dim3(4, 512), 256, GEMM_SMEM>>>();
    att_mma<<<dim3(H_, NC_, B_), 256, ATT_SMEM>>>();
    merge_kernel<<<dim3(P_, H_, B_), 512>>>();
    proj_kernel<<<dim3(P_, B_), 512>>>();
    topk_kernel<<<B_, 256>>>();
    mlp_kernel<<<dim3(4, B_), 128>>>(0, W1, b1, nullptr, 1);
    mlp_kernel<<<dim3(4, B_), 128>>>(1, W2, b2, out, 0);
}

// round 13
// speedup vs baseline: 2.7638x; 1.0662x over previous
#include <cuda_runtime.h>
#include <cuda_fp16.h>
#include <cstdint>
#include <cstddef>

#define B_    8
#define T_    8192
#define D_    512
#define H_    4
#define P_    24
#define HD_   128
#define TOPK_ 12
#define NC_   16
#define CHUNK_ 512
#define PSTR  514   // per-proto partial stride: m, l, U[512]

// ---------------- scratch (static device globals; no allocation) ----------------
__device__ __align__(16) __half g_xh[(size_t)B_ * T_ * D_];   // xn (fp16)
__device__ __align__(16) __half g_Wh[2 * D_ * D_];            // Wk, Wv (fp16)
__device__ __align__(16) __half g_K [(size_t)B_ * T_ * D_];   // K (fp16)
__device__ float g_Qh[H_ * P_ * HD_];
__device__ float g_part[(size_t)B_ * H_ * NC_ * P_ * PSTR];
__device__ float g_U [(size_t)B_ * H_ * P_ * D_];
__device__ float g_pt[B_ * P_ * D_];
__device__ float g_z [B_ * D_];
__device__ float g_hid[B_ * D_];

// ---------------- helpers ----------------
__device__ __forceinline__ uint32_t smem_u32(const void* p) {
    uint32_t a;
    asm("{ .reg .u64 t; cvta.to.shared.u64 t, %1; cvt.u32.u64 %0, t; }" : "=r"(a) : "l"(p));
    return a;
}
__device__ __forceinline__ void cp16(uint32_t s, const void* g) {
    asm volatile("cp.async.cg.shared.global [%0], [%1], 16;" :: "r"(s), "l"(g) : "memory");
}
__device__ __forceinline__ void cp_commit() {
    asm volatile("cp.async.commit_group;" ::: "memory");
}
template <int N> __device__ __forceinline__ void cp_wait() {
    asm volatile("cp.async.wait_group %0;" :: "n"(N) : "memory");
}
__device__ __forceinline__ void ldsm4(uint32_t& r0, uint32_t& r1, uint32_t& r2, uint32_t& r3,
                                      uint32_t addr) {
    asm volatile("ldmatrix.sync.aligned.m8n8.x4.shared.b16 {%0,%1,%2,%3}, [%4];"
                 : "=r"(r0), "=r"(r1), "=r"(r2), "=r"(r3) : "r"(addr));
}
__device__ __forceinline__ void ldsm4t(uint32_t& r0, uint32_t& r1, uint32_t& r2, uint32_t& r3,
                                       uint32_t addr) {
    asm volatile("ldmatrix.sync.aligned.m8n8.x4.trans.shared.b16 {%0,%1,%2,%3}, [%4];"
                 : "=r"(r0), "=r"(r1), "=r"(r2), "=r"(r3) : "r"(addr));
}
__device__ __forceinline__ void mma_f16(float* c,
                                        uint32_t a0, uint32_t a1, uint32_t a2, uint32_t a3,
                                        uint32_t b0, uint32_t b1) {
    asm volatile("mma.sync.aligned.m16n8k16.row.col.f32.f16.f16.f32 "
                 "{%0,%1,%2,%3}, {%4,%5,%6,%7}, {%8,%9}, {%0,%1,%2,%3};"
                 : "+f"(c[0]), "+f"(c[1]), "+f"(c[2]), "+f"(c[3])
                 : "r"(a0), "r"(a1), "r"(a2), "r"(a3), "r"(b0), "r"(b1));
}
__device__ __forceinline__ void h8_unpack(uint4 r, float* o, float& nn) {
    float2 f;
    f = __half22float2(*(__half2*)&r.x); o[0] = f.x; o[1] = f.y; nn += f.x * f.x + f.y * f.y;
    f = __half22float2(*(__half2*)&r.y); o[2] = f.x; o[3] = f.y; nn += f.x * f.x + f.y * f.y;
    f = __half22float2(*(__half2*)&r.z); o[4] = f.x; o[5] = f.y; nn += f.x * f.x + f.y * f.y;
    f = __half22float2(*(__half2*)&r.w); o[6] = f.x; o[7] = f.y; nn += f.x * f.x + f.y * f.y;
}

// ---------------- 1. LayerNorm -> fp16 ----------------
__global__ __launch_bounds__(256) void ln_kernel(const float* __restrict__ x,
                                                 const float* __restrict__ gw,
                                                 const float* __restrict__ bw) {
    int lane = threadIdx.x & 31;
    size_t row = (size_t)blockIdx.x * 8 + (threadIdx.x >> 5);
    const float* xr = x + row * D_;
    float4 v[4];
    float s = 0.f, sq = 0.f;
#pragma unroll
    for (int j = 0; j < 4; j++) {
        v[j] = *(const float4*)&xr[lane * 4 + j * 128];
        s  += v[j].x + v[j].y + v[j].z + v[j].w;
        sq += v[j].x * v[j].x + v[j].y * v[j].y + v[j].z * v[j].z + v[j].w * v[j].w;
    }
#pragma unroll
    for (int o = 16; o > 0; o >>= 1) {
        s  += __shfl_xor_sync(0xffffffffu, s,  o);
        sq += __shfl_xor_sync(0xffffffffu, sq, o);
    }
    float mu   = s * (1.f / 512.f);
    float var  = sq * (1.f / 512.f) - mu * mu;
    float rstd = rsqrtf(var + 1e-5f);
#pragma unroll
    for (int j = 0; j < 4; j++) {
        int c = lane * 4 + j * 128;
        float4 gv = *(const float4*)&gw[c];
        float4 bv = *(const float4*)&bw[c];
        __half h[4];
        h[0] = __float2half_rn((v[j].x - mu) * rstd * gv.x + bv.x);
        h[1] = __float2half_rn((v[j].y - mu) * rstd * gv.y + bv.y);
        h[2] = __float2half_rn((v[j].z - mu) * rstd * gv.z + bv.z);
        h[3] = __float2half_rn((v[j].w - mu) * rstd * gv.w + bv.w);
        *(uint2*)&g_xh[row * D_ + c] = *(uint2*)h;
    }
}

// ---------------- 1b. W matrices -> fp16 ----------------
__global__ __launch_bounds__(256) void round_w(const float* __restrict__ Wk,
                                               const float* __restrict__ Wv) {
    int i = blockIdx.x * 256 + threadIdx.x;
    g_Wh[i]           = __float2half_rn(Wk[i]);
    g_Wh[D_ * D_ + i] = __float2half_rn(Wv[i]);
}

// ---------------- 2. fp16 mma GEMM: K = xn @ Wk^T (K projection ONLY) ----------------
#define ROWB 80
#define TILE_B (128 * ROWB)
#define STAGE_B (2 * TILE_B)
#define GEMM_SMEM (3 * STAGE_B)    // 61440 B

__global__ __launch_bounds__(256, 2) void gemm_f16() {
    extern __shared__ __align__(16) char smc[];
    const uint32_t sb = smem_u32(smc);

    const int tid = threadIdx.x;
    const int wid = tid >> 5, lane = tid & 31;
    const int n0 = blockIdx.x * 128;
    const size_t m0 = (size_t)blockIdx.y * 128;

    const __half* A_g = g_xh;
    const __half* B_g = g_Wh;           // Wk
    __half* C = g_K;

    const int lrow = tid >> 1;
    const int lch  = tid & 1;
    const size_t gA = (m0 + lrow) * D_ + lch * 16;
    const size_t gB = (size_t)(n0 + lrow) * D_ + lch * 16;
    const uint32_t sRow = (uint32_t)lrow * ROWB + lch * 32;

    const int wm = (wid >> 2) * 64;
    const int wn = (wid & 3) * 32;
    const int g  = lane >> 2;
    const int t  = lane & 3;

    uint32_t aRow[4], bRow[2];
#pragma unroll
    for (int mi = 0; mi < 4; mi++)
        aRow[mi] = (uint32_t)(wm + mi * 16 + (lane & 15)) * ROWB + ((lane & 16) ? 16 : 0);
#pragma unroll
    for (int np = 0; np < 2; np++)
        bRow[np] = (uint32_t)(wn + np * 16 + ((lane & 16) ? 8 : 0) + (lane & 7)) * ROWB
                   + ((lane & 8) ? 16 : 0);

    float c[4][4][4];
#pragma unroll
    for (int mi = 0; mi < 4; mi++)
#pragma unroll
        for (int ni = 0; ni < 4; ni++)
#pragma unroll
            for (int j = 0; j < 4; j++) c[mi][ni][j] = 0.f;

    auto stage = [&](int st, int kt) {
        uint32_t bbA = sb + (uint32_t)st * STAGE_B;
        uint32_t bbB = bbA + TILE_B;
        int ke = kt * 32;
        cp16(bbA + sRow,      A_g + gA + ke);
        cp16(bbA + sRow + 16, A_g + gA + ke + 8);
        cp16(bbB + sRow,      B_g + gB + ke);
        cp16(bbB + sRow + 16, B_g + gB + ke + 8);
        cp_commit();
    };

    stage(0, 0);
    stage(1, 1);

#pragma unroll 1
    for (int kt = 0; kt < 16; ++kt) {
        if (kt < 15) cp_wait<1>(); else cp_wait<0>();
        __syncthreads();
        if (kt + 2 < 16) stage((kt + 2) % 3, kt + 2);

        const uint32_t bbA = sb + (uint32_t)(kt % 3) * STAGE_B;
        const uint32_t bbB = bbA + TILE_B;

#pragma unroll
        for (int ks = 0; ks < 2; ks++) {
            const uint32_t ko = ks * 32;
            uint32_t a[4][4], bq[2][4];
#pragma unroll
            for (int mi = 0; mi < 4; mi++)
                ldsm4(a[mi][0], a[mi][1], a[mi][2], a[mi][3], bbA + aRow[mi] + ko);
#pragma unroll
            for (int np = 0; np < 2; np++)
                ldsm4(bq[np][0], bq[np][1], bq[np][2], bq[np][3], bbB + bRow[np] + ko);
#pragma unroll
            for (int mi = 0; mi < 4; mi++)
#pragma unroll
                for (int np = 0; np < 2; np++) {
                    mma_f16(c[mi][np * 2],     a[mi][0], a[mi][1], a[mi][2], a[mi][3],
                            bq[np][0], bq[np][1]);
                    mma_f16(c[mi][np * 2 + 1], a[mi][0], a[mi][1], a[mi][2], a[mi][3],
                            bq[np][2], bq[np][3]);
                }
        }
    }

#pragma unroll
    for (int mi = 0; mi < 4; mi++) {
#pragma unroll
        for (int ni = 0; ni < 4; ni++) {
            size_t r0 = m0 + wm + mi * 16 + g;
            int col = n0 + wn + ni * 8 + t * 2;
            *(__half2*)&C[r0 * D_ + col]       = __floats2half2_rn(c[mi][ni][0], c[mi][ni][1]);
            *(__half2*)&C[(r0 + 8) * D_ + col] = __floats2half2_rn(c[mi][ni][2], c[mi][ni][3]);
        }
    }
}

// ---------------- 3. Qh: grid (P, H), 512 threads ----------------
__global__ __launch_bounds__(512) void qh_kernel(const float* __restrict__ proto,
                                                 const float* __restrict__ Wq) {
    __shared__ float pr[D_];
    __shared__ float qp[HD_];
    __shared__ float sinv;
    int p = blockIdx.x, h = blockIdx.y, tid = threadIdx.x;
    pr[tid] = proto[p * D_ + tid];
    __syncthreads();
    int nl = tid >> 2, part = tid & 3;
    const float* wr = Wq + (size_t)(h * HD_ + nl) * D_ + part * 128;
    const float* pp = pr + part * 128;
    float a = 0.f;
#pragma unroll 8
    for (int k = 0; k < 128; k += 4) {
        float4 w4 = *(const float4*)&wr[k];
        a += w4.x * pp[k] + w4.y * pp[k + 1] + w4.z * pp[k + 2] + w4.w * pp[k + 3];
    }
    a += __shfl_xor_sync(0xffffffffu, a, 1);
    a += __shfl_xor_sync(0xffffffffu, a, 2);
    if (part == 0) qp[nl] = a;
    __syncthreads();
    if (tid < 32) {
        float sq = 0.f;
#pragma unroll
        for (int j = 0; j < 4; j++) { float tv = qp[tid + 32 * j]; sq += tv * tv; }
#pragma unroll
        for (int o = 16; o > 0; o >>= 1) sq += __shfl_xor_sync(0xffffffffu, sq, o);
        if (tid == 0) sinv = 1.f / fmaxf(sqrtf(sq), 1e-12f);
    }
    __syncthreads();
    if (tid < HD_) g_Qh[(h * P_ + p) * HD_ + tid] = qp[tid] * sinv;
}

// ---------------- 4. attention; PV against xn; fp16 in-place score/P buffer ----------------
// grid (H, NC, B), 256 threads. smem 113920 B -> 2 CTAs/SM.
#define oQ   0
#define oKB  8704
#define KBUF 34816
#define oSP  78336
#define oNm  111616
#define oMs  113664
#define oLs  113792
#define ATT_SMEM 113920

__global__ __launch_bounds__(256, 2) void att_mma() {
    extern __shared__ __align__(16) char smc[];
    const uint32_t sb = smem_u32(smc);
    __half* Qs = (__half*)(smc + oQ);
    __half* SP = (__half*)(smc + oSP);     // scores then exp-weights, fp16, 32 x 520
    float*  Nm = (float*)(smc + oNm);
    float*  Ms = (float*)(smc + oMs);
    float*  Ls = (float*)(smc + oLs);
    const uint32_t* Qw = (const uint32_t*)Qs;
    const uint32_t* Pw = (const uint32_t*)SP;

    const int tid = threadIdx.x;
    const int wid = tid >> 5, lane = tid & 31;
    const int g = lane >> 2, t = lane & 3;
    const int h = blockIdx.x, cz = blockIdx.y, b = blockIdx.z;
    const size_t tokbase = (size_t)(b * T_ + cz * CHUNK_);

    for (int i = tid; i < 32 * 128; i += 256) {
        int p = i >> 7, d = i & 127;
        float v = (p < P_) ? g_Qh[(h * P_ + p) * HD_ + d] : 0.f;
        Qs[p * 136 + d] = __float2half_rn(v);
    }

    auto stageK = [&](int st, int bf) {
        uint32_t bb = sb + oKB + (uint32_t)bf * KBUF;
#pragma unroll
        for (int j = 0; j < 8; j++) {
            int lin = tid + 256 * j;
            int tok = lin >> 4, ch = lin & 15;
            cp16(bb + (uint32_t)(tok * 136 + ch * 8) * 2,
                 g_K + (tokbase + st * 128 + tok) * D_ + h * HD_ + ch * 8);
        }
        cp_commit();
    };
    auto stageXN = [&](int dg, int st, int bf) {
        uint32_t bb = sb + oKB + (uint32_t)bf * KBUF;
#pragma unroll
        for (int j = 0; j < 8; j++) {
            int lin = tid + 256 * j;
            int tok = lin >> 4, ch = lin & 15;
            cp16(bb + (uint32_t)(tok * 136 + ch * 8) * 2,
                 g_xh + (tokbase + st * 128 + tok) * D_ + dg * 128 + ch * 8);
        }
        cp_commit();
    };

    stageK(0, 0);
    stageK(1, 1);

    // ================= scores (fp16 into SP) =================
#pragma unroll 1
    for (int st = 0; st < 4; ++st) {
        cp_wait<1>();
        __syncthreads();
        const __half*   Kh = (const __half*)(smc + oKB + (st & 1) * KBUF);
        const uint32_t* Kw = (const uint32_t*)Kh;

        {
            int tok = tid >> 1, hf = tid & 1;
            const uint4* kp = (const uint4*)(Kh + tok * 136 + hf * 64);
            float nn = 0.f, tmp[8];
#pragma unroll
            for (int i = 0; i < 8; i++) h8_unpack(kp[i], tmp, nn);
            nn += __shfl_xor_sync(0xffffffffu, nn, 1);
            if (hf == 0) Nm[st * 128 + tok] = nn;
        }
        __syncthreads();

        float c[2][2][4] = {};
#pragma unroll
        for (int kt = 0; kt < 8; kt++) {
            uint32_t a[2][4];
#pragma unroll
            for (int mi = 0; mi < 2; mi++) {
                int base = (mi * 16 + g) * 68 + kt * 8 + t;
                a[mi][0] = Qw[base];
                a[mi][1] = Qw[base + 8 * 68];
                a[mi][2] = Qw[base + 4];
                a[mi][3] = Qw[base + 8 * 68 + 4];
            }
#pragma unroll
            for (int np = 0; np < 2; np++) {
                int tok = wid * 16 + np * 8 + g;
                int base = tok * 68 + kt * 8 + t;
                uint32_t b0 = Kw[base], b1 = Kw[base + 4];
#pragma unroll
                for (int mi = 0; mi < 2; mi++)
                    mma_f16(c[mi][np], a[mi][0], a[mi][1], a[mi][2], a[mi][3], b0, b1);
            }
        }
#pragma unroll
        for (int np = 0; np < 2; np++) {
            int tc = wid * 16 + np * 8 + t * 2;
            float inv0 = 1.f / (fmaxf(sqrtf(Nm[st * 128 + tc]),     1e-12f) * 0.07f);
            float inv1 = 1.f / (fmaxf(sqrtf(Nm[st * 128 + tc + 1]), 1e-12f) * 0.07f);
#pragma unroll
            for (int mi = 0; mi < 2; mi++) {
                int r0 = mi * 16 + g;
                *(__half2*)&SP[r0 * 520 + st * 128 + tc] =
                    __floats2half2_rn(c[mi][np][0] * inv0, c[mi][np][1] * inv1);
                *(__half2*)&SP[(r0 + 8) * 520 + st * 128 + tc] =
                    __floats2half2_rn(c[mi][np][2] * inv0, c[mi][np][3] * inv1);
            }
        }
        __syncthreads();
        if (st < 2) stageK(st + 2, st & 1);
        else        stageXN(0, st - 2, st & 1);   // PV stages ls=0,1
    }

    // ================= softmax in place on SP (rows 24-31 benign) =================
#pragma unroll 1
    for (int rr = 0; rr < 4; ++rr) {
        int p = wid + rr * 8;
        float vals[16];
        float m = -3.4e38f;
#pragma unroll
        for (int j = 0; j < 16; j++) {
            vals[j] = __half2float(SP[p * 520 + lane + 32 * j]);
            m = fmaxf(m, vals[j]);
        }
#pragma unroll
        for (int o = 16; o > 0; o >>= 1) m = fmaxf(m, __shfl_xor_sync(0xffffffffu, m, o));
        float s = 0.f;
#pragma unroll
        for (int j = 0; j < 16; j++) {
            float e = expf(vals[j] - m);
            SP[p * 520 + lane + 32 * j] = __float2half_rn(e);
            s += e;
        }
#pragma unroll
        for (int o = 16; o > 0; o >>= 1) s += __shfl_xor_sync(0xffffffffu, s, o);
        if (lane == 0) { Ms[p] = m; Ls[p] = s; }
    }

    // ================= PV: U = P @ xn, 4 dgroups x 4 token sub-tiles =================
    size_t base = (((size_t)(b * H_ + h) * NC_ + cz) * P_) * PSTR;
    float cp2[2][2][4] = {};
#pragma unroll 1
    for (int ls = 0; ls < 16; ++ls) {
        int dg = ls >> 2, st = ls & 3;
        if (ls < 15) cp_wait<1>(); else cp_wait<0>();
        __syncthreads();
        uint32_t vb = sb + oKB + (uint32_t)(ls & 1) * KBUF;

#pragma unroll
        for (int kt = 0; kt < 8; kt++) {
            uint32_t a[2][4];
#pragma unroll
            for (int mi = 0; mi < 2; mi++) {
                int abase = (mi * 16 + g) * 260 + st * 64 + kt * 8 + t;
                a[mi][0] = Pw[abase];
                a[mi][1] = Pw[abase + 8 * 260];
                a[mi][2] = Pw[abase + 4];
                a[mi][3] = Pw[abase + 8 * 260 + 4];
            }
            uint32_t r0, r1, r2, r3;
            uint32_t addr = vb + (uint32_t)((kt * 16 + (lane & 15)) * 136 +
                                            wid * 16 + ((lane & 16) ? 8 : 0)) * 2;
            ldsm4t(r0, r1, r2, r3, addr);
#pragma unroll
            for (int mi = 0; mi < 2; mi++) {
                mma_f16(cp2[mi][0], a[mi][0], a[mi][1], a[mi][2], a[mi][3], r0, r1);
                mma_f16(cp2[mi][1], a[mi][0], a[mi][1], a[mi][2], a[mi][3], r2, r3);
            }
        }
        __syncthreads();
        if (ls + 2 < 16) stageXN((ls + 2) >> 2, (ls + 2) & 3, ls & 1);

        if (st == 3) {
#pragma unroll
            for (int mi = 0; mi < 2; mi++)
#pragma unroll
                for (int np = 0; np < 2; np++)
#pragma unroll
                    for (int j = 0; j < 4; j++) {
                        int r = mi * 16 + g + ((j >> 1) ? 8 : 0);
                        if (r < P_) {
                            int col = dg * 128 + wid * 16 + np * 8 + t * 2 + (j & 1);
                            g_part[base + (size_t)r * PSTR + 2 + col] = cp2[mi][np][j];
                        }
                        cp2[mi][np][j] = 0.f;
                    }
        }
    }
    if (tid < P_) {
        g_part[base + (size_t)tid * PSTR]     = Ms[tid];
        g_part[base + (size_t)tid * PSTR + 1] = Ls[tid];
    }
}

// ---------------- 5. merge chunk partials -> U ----------------
__global__ __launch_bounds__(512) void merge_kernel() {
    int p = blockIdx.x, h = blockIdx.y, b = blockIdx.z;
    int d = threadIdx.x;
    float M = -3.4e38f;
    for (int c = 0; c < NC_; c++) {
        const float* pp = g_part + (((size_t)(b * H_ + h) * NC_ + c) * P_ + p) * PSTR;
        M = fmaxf(M, pp[0]);
    }
    float L = 0.f, val = 0.f;
    for (int c = 0; c < NC_; c++) {
        const float* pp = g_part + (((size_t)(b * H_ + h) * NC_ + c) * P_ + p) * PSTR;
        float wgt = expf(pp[0] - M);
        L   += pp[1] * wgt;
        val += pp[2 + d] * wgt;
    }
    float out = (L > 0.f) ? val / L : 0.f;
    g_U[(((size_t)b * H_ + h) * P_ + p) * D_ + d] = out;
}

// ---------------- 5b. project: proto_tokens = U @ Wv_h^T ----------------
__global__ __launch_bounds__(512) void proj_kernel() {
    __shared__ float Us[H_ * D_];
    int p = blockIdx.x, b = blockIdx.y, tid = threadIdx.x;
    for (int i = tid; i < H_ * D_; i += 512) {
        int h = i >> 9, k = i & 511;
        Us[i] = g_U[(((size_t)b * H_ + h) * P_ + p) * D_ + k];
    }
    __syncthreads();
    int h = tid >> 7, dd = tid & 127;
    const __half* wr = g_Wh + (size_t)D_ * D_ + (size_t)(h * HD_ + dd) * D_;  // Wv row
    const float* u = Us + h * D_;
    float s = 0.f;
#pragma unroll 8
    for (int k = 0; k < D_; k += 8) {
        uint4 r = *(const uint4*)(wr + k);
        float w[8], dmy = 0.f;
        h8_unpack(r, w, dmy);
        s += w[0] * u[k]     + w[1] * u[k + 1] + w[2] * u[k + 2] + w[3] * u[k + 3]
           + w[4] * u[k + 4] + w[5] * u[k + 5] + w[6] * u[k + 6] + w[7] * u[k + 7];
    }
    g_pt[(b * P_ + p) * D_ + h * HD_ + dd] = s;
}

// ---------------- 6. topk ----------------
__global__ __launch_bounds__(256) void topk_kernel() {
    int b = blockIdx.x, tid = threadIdx.x, w = tid >> 5, lane = tid & 31;
    __shared__ float ss[P_];
    __shared__ int idxs[TOPK_];
#pragma unroll 1
    for (int rr = 0; rr < 3; rr++) {
        int p = w + rr * 8;
        const float* pr = g_pt + (b * P_ + p) * D_;
        float sq = 0.f;
#pragma unroll
        for (int j = 0; j < 16; j++) { float tv = pr[lane + 32 * j]; sq += tv * tv; }
#pragma unroll
        for (int o = 16; o > 0; o >>= 1) sq += __shfl_xor_sync(0xffffffffu, sq, o);
        if (lane == 0) ss[p] = sq;
    }
    __syncthreads();
    if (tid == 0) {
        unsigned used = 0;
        for (int i = 0; i < TOPK_; i++) {
            int best = -1; float bv = -3.4e38f;
            for (int p = 0; p < P_; p++)
                if (!((used >> p) & 1) && ss[p] > bv) { bv = ss[p]; best = p; }
            used |= 1u << best;
            idxs[i] = best;
        }
    }
    __syncthreads();
    for (int d = tid; d < D_; d += 256) {
        float s = 0.f;
        for (int i = 0; i < TOPK_; i++) s += g_pt[(b * P_ + idxs[i]) * D_ + d];
        g_z[b * D_ + d] = s * (1.f / TOPK_);
    }
}

// ---------------- 7. MLP ----------------
__global__ __launch_bounds__(128) void mlp_kernel(int in_sel, const float* __restrict__ W,
                                                  const float* __restrict__ bias,
                                                  float* __restrict__ out_ext, int act) {
    __shared__ float zs[D_];
    int b = blockIdx.y, tid = threadIdx.x;
    int n = blockIdx.x * 128 + tid;
    const float* in = in_sel ? g_hid : g_z;
    for (int i = tid; i < D_; i += 128) zs[i] = in[b * D_ + i];
    __syncthreads();
    const float* wr = W + (size_t)n * D_;
    float s = bias[n];
    for (int k = 0; k < D_; k += 4) {
        float4 w4 = *(const float4*)&wr[k];
        s += w4.x * zs[k] + w4.y * zs[k + 1] + w4.z * zs[k + 2] + w4.w * zs[k + 3];
    }
    if (act) s = s / (1.f + expf(-s));
    float* out = out_ext ? out_ext : g_hid;
    out[b * D_ + n] = s;
}

// ---------------- launch ----------------
extern "C" void kernel_launch(void* const* d_in, const int* in_sizes, int n_in,
                              void* d_out, int out_size) {
    (void)in_sizes; (void)n_in; (void)out_size;
    const float* x     = (const float*)d_in[0];
    const float* proto = (const float*)d_in[1];
    const float* ln_g  = (const float*)d_in[2];
    const float* ln_b  = (const float*)d_in[3];
    const float* Wq    = (const float*)d_in[4];
    const float* Wk    = (const float*)d_in[5];
    const float* Wv    = (const float*)d_in[6];
    const float* W1    = (const float*)d_in[7];
    const float* b1    = (const float*)d_in[8];
    const float* W2    = (const float*)d_in[9];
    const float* b2    = (const float*)d_in[10];
    float* out = (float*)d_out;

    cudaFuncSetAttribute(gemm_f16, cudaFuncAttributeMaxDynamicSharedMemorySize, GEMM_SMEM);
    cudaFuncSetAttribute(att_mma, cudaFuncAttributeMaxDynamicSharedMemorySize, ATT_SMEM);

    ln_kernel<<<(B_ * T_) / 8, 256>>>(x, ln_g, ln_b);
    round_w<<<(D_ * D_) / 256, 256>>>(Wk, Wv);
    qh_kernel<<<dim3(P_, H_), 512>>>(proto, Wq);
    gemm_f16<<<dim3(4, 512), 256, GEMM_SMEM>>>();
    att_mma<<<dim3(H_, NC_, B_), 256, ATT_SMEM>>>();
    merge_kernel<<<dim3(P_, H_, B_), 512>>>();
    proj_kernel<<<dim3(P_, B_), 512>>>();
    topk_kernel<<<B_, 256>>>();
    mlp_kernel<<<dim3(4, B_), 128>>>(0, W1, b1, nullptr, 1);
    mlp_kernel<<<dim3(4, B_), 128>>>(1, W2, b2, out, 0);
}